// round 13
// baseline (speedup 1.0000x reference)
#include <cuda_runtime.h>
#include <cuda_bf16.h>
#include <cstdint>

typedef unsigned long long ull;
typedef unsigned short u16;
typedef unsigned int u32;

// ---------------- device scratch (static, zero-initialized) ----------------
__device__ __align__(16) u16   g_s1p[2048 * 18 * 18 * 2 * 32]; // conv1 out packed, halo 0
__device__ __align__(16) u16   g_s2h[2048 * 3136];          // conv2 out bf16 hi [b][q*64+co]
__device__ __align__(16) u16   g_s2l[2048 * 3136];          // conv2 out bf16 lo
__device__ __align__(16) float g_fc1p[2 * 2048 * 1024];     // fc1 split-K partials
__device__ __align__(16) u16   g_fc1wh[1024 * 3136];        // fc1 w bf16 hi, K (q,co)
__device__ __align__(16) u16   g_fc1wl[1024 * 3136];        // fc1 w bf16 lo
__device__ __align__(16) u16   g_w2b[5 * 2 * 64 * 168];     // conv2 B [dy][plane][n][k pad 168]

// ---------------- f32x2 helpers ----------------
__device__ __forceinline__ ull ffma2(ull a, ull b, ull c) {
    ull d; asm("fma.rn.f32x2 %0, %1, %2, %3;" : "=l"(d) : "l"(a), "l"(b), "l"(c)); return d;
}
__device__ __forceinline__ ull dup2(float v) {
    ull d; asm("mov.b64 %0, {%1, %1};" : "=l"(d) : "f"(v)); return d;
}
__device__ __forceinline__ ull pk2(float lo, float hi) {
    ull d; asm("mov.b64 %0, {%1, %2};" : "=l"(d) : "f"(lo), "f"(hi)); return d;
}
__device__ __forceinline__ void upk2(ull v, float& lo, float& hi) {
    asm("mov.b64 {%0, %1}, %2;" : "=f"(lo), "=f"(hi) : "l"(v));
}

// ---------------- cp.async ----------------
__device__ __forceinline__ void cp16u(u32 saddr, const void* g) {
    asm volatile("cp.async.ca.shared.global [%0], [%1], 16;" :: "r"(saddr), "l"(g));
}
__device__ __forceinline__ void cp_commit() { asm volatile("cp.async.commit_group;"); }
__device__ __forceinline__ void cp_wait0()  { asm volatile("cp.async.wait_group 0;"); }
__device__ __forceinline__ void cp_wait1()  { asm volatile("cp.async.wait_group 1;"); }

// ---------------- mma.sync / ldmatrix ----------------
__device__ __forceinline__ void ldsm4(u32& r0, u32& r1, u32& r2, u32& r3, u32 addr) {
    asm volatile("ldmatrix.sync.aligned.m8n8.x4.shared.b16 {%0,%1,%2,%3}, [%4];"
                 : "=r"(r0), "=r"(r1), "=r"(r2), "=r"(r3) : "r"(addr));
}
__device__ __forceinline__ void mma16816(float* d, const u32* a, const u32* b) {
    asm volatile("mma.sync.aligned.m16n8k16.row.col.f32.bf16.bf16.f32 "
                 "{%0,%1,%2,%3}, {%4,%5,%6,%7}, {%8,%9}, {%0,%1,%2,%3};"
                 : "+f"(d[0]), "+f"(d[1]), "+f"(d[2]), "+f"(d[3])
                 : "r"(a[0]), "r"(a[1]), "r"(a[2]), "r"(a[3]), "r"(b[0]), "r"(b[1]));
}

__device__ __forceinline__ void ins4(float& a, float& b, float& c, float& d, float v) {
    if (v > d) {
        d = v;
        if (d > c) { float t = c; c = d; d = t;
            if (c > b) { t = b; b = c; c = t;
                if (b > a) { t = a; a = b; b = t; }
            }
        }
    }
}
__device__ __forceinline__ u32 bf16pack2(float x, float y) {
    __nv_bfloat16 hx = __float2bfloat16(x), hy = __float2bfloat16(y);
    return (u32)reinterpret_cast<u16&>(hx) | ((u32)reinterpret_cast<u16&>(hy) << 16);
}

// ============================================================================
// merged prep: blocks [0,1024) = fc1 weight permute+split; blocks [1024,1444)
// = conv2 B image build.
// ============================================================================
__global__ void __launch_bounds__(256) k_prep(const float* __restrict__ w2,
                                              const float* __restrict__ wfc) {
    __shared__ float row[3136];
    if (blockIdx.x < 1024) {
        int n = blockIdx.x;
        for (int i = threadIdx.x; i < 3136; i += 256) row[i] = wfc[n * 3136 + i];
        __syncthreads();
        for (int i = threadIdx.x; i < 3136; i += 256) {
            int q = i >> 6, co = i & 63;
            float v = row[co * 49 + q];
            __nv_bfloat16 h = __float2bfloat16(v);
            __nv_bfloat16 l2 = __float2bfloat16(v - __bfloat162float(h));
            g_fc1wh[n * 3136 + i] = reinterpret_cast<u16&>(h);
            g_fc1wl[n * 3136 + i] = reinterpret_cast<u16&>(l2);
        }
    } else {
        int i = (blockIdx.x - 1024) * 256 + threadIdx.x;
        if (i >= 5 * 2 * 64 * 168) return;
        int dy = i / 21504, r = i % 21504;
        int plane = r / 10752, r2 = r % 10752;
        int co = r2 / 168, k = r2 % 168;
        float v = 0.f;
        if (k < 160) {
            int dx = k >> 5, ci = k & 31;
            v = w2[(co * 32 + ci) * 25 + dy * 5 + dx];
        }
        __nv_bfloat16 h = __float2bfloat16(v);
        if (plane == 0) {
            g_w2b[i] = reinterpret_cast<u16&>(h);
        } else {
            __nv_bfloat16 l2 = __float2bfloat16(v - __bfloat162float(h));
            g_w2b[i] = reinterpret_cast<u16&>(l2);
        }
    }
}

// ============================================================================
// conv1 (1->32, 5x5, pad2) + top-4 mask + threshold ReLU + 2x2 maxpool.
// SINGLE pass: CTA = 784 threads = 1 image, thread = 1 pixel (quad-major).
// ============================================================================
__global__ void __launch_bounds__(784) k_conv1(const float* __restrict__ xin,
                                               const float* __restrict__ w1,
                                               const float* __restrict__ tt) {
    __shared__ float s_img[1024];
    __shared__ ull   s_wp[400];
    __shared__ float s_t[32];

    const int tid = threadIdx.x;
    const int img = blockIdx.x;

    for (int i = tid; i < 1024; i += 784) s_img[i] = 0.f;
    for (int i = tid; i < 400; i += 784) {
        int tap = i >> 4, c16 = i & 15;
        s_wp[i] = pk2(w1[(2 * c16) * 25 + tap], w1[(2 * c16 + 1) * 25 + tap]);
    }
    if (tid < 32) s_t[tid] = tt[tid];
    __syncthreads();
    {
        int y = tid / 28, xx = tid % 28;
        s_img[(y + 2) * 32 + xx + 2] = xin[img * 784 + tid];
    }
    __syncthreads();

    const int q = tid >> 2, j = tid & 3;
    const int PY = q / 14, PX = q % 14;
    const int py = 2 * PY + (j >> 1), px = 2 * PX + (j & 1);
    const float* base = &s_img[py * 32 + px];

    ull acc[16];
#pragma unroll
    for (int c = 0; c < 16; c++) acc[c] = 0ull;
#pragma unroll
    for (int dy = 0; dy < 5; dy++)
#pragma unroll
        for (int dx = 0; dx < 5; dx++) {
            ull wd = dup2(base[dy * 32 + dx]);
            const ull* wp = &s_wp[(dy * 5 + dx) * 16];
#pragma unroll
            for (int c = 0; c < 16; c++) acc[c] = ffma2(wd, wp[c], acc[c]);
        }

    float vals[32];
#pragma unroll
    for (int c = 0; c < 16; c++) upk2(acc[c], vals[2 * c], vals[2 * c + 1]);

    float a4 = -3.4e38f, b4 = -3.4e38f, c4 = -3.4e38f, d4 = -3.4e38f;
#pragma unroll
    for (int c = 0; c < 32; c++) ins4(a4, b4, c4, d4, vals[c]);

    const u32 lane = (u32)(tid & 31);
    const u32 qm = 0xFu << (lane & ~3u);
#pragma unroll
    for (int c = 0; c < 32; c++) {
        float v = vals[c];
        float r = (v >= d4) ? fmaxf(v - s_t[c], 0.f) : 0.f;
        r = fmaxf(r, __shfl_xor_sync(qm, r, 1));
        r = fmaxf(r, __shfl_xor_sync(qm, r, 2));
        vals[c] = r;
    }

    if (j == 0) {
        u16 oh[32], ol[32];
#pragma unroll
        for (int c = 0; c < 32; c++) {
            float v = vals[c];
            __nv_bfloat16 h = __float2bfloat16(v);
            oh[c] = reinterpret_cast<u16&>(h);
            __nv_bfloat16 l2 = __float2bfloat16(v - __bfloat162float(h));
            ol[c] = reinterpret_cast<u16&>(l2);
        }
        size_t gb = ((((size_t)img * 18 + (PY + 2)) * 18 + (PX + 2)) * 2) * 32;
#pragma unroll
        for (int g = 0; g < 2; g++) {
#pragma unroll
            for (int c = 0; c < 4; c++) {
                __align__(16) u16 buf[8];
                buf[0] = oh[g * 16 + 2 * c];     buf[1] = oh[g * 16 + 2 * c + 1];
                buf[2] = ol[g * 16 + 2 * c];     buf[3] = ol[g * 16 + 2 * c + 1];
                buf[4] = oh[g * 16 + 2 * c + 8]; buf[5] = oh[g * 16 + 2 * c + 9];
                buf[6] = ol[g * 16 + 2 * c + 8]; buf[7] = ol[g * 16 + 2 * c + 9];
                *reinterpret_cast<uint4*>(g_s1p + gb + g * 32 + c * 8) =
                    *reinterpret_cast<uint4*>(buf);
            }
        }
    }
}

// ============================================================================
// conv2 via mma.sync (bf16 hi/lo x3): 5 accumulated GEMMs, K=160 per dy.
// CTA = 256 threads / 8 warps, M=256 rows; warp = m32 x n64, 2 CTAs/SM.
// ============================================================================
__global__ void __launch_bounds__(256, 2) k_conv2(const float* __restrict__ b2) {
    extern __shared__ __align__(16) char sm2[];
    u32 sB = (u32)__cvta_generic_to_shared(sm2);   // 2 x 43008 B buffers

    const int tid = threadIdx.x;
    const int warp = tid >> 5, lane = tid & 31;

    u32 grpb[4];
#pragma unroll
    for (int i = 0; i < 4; i++) {
        int r = warp * 32 + ((i & 1) << 3) + ((i >> 1) << 4) + (lane >> 2);
        int m = blockIdx.x * 256 + r;
        int g = m >> 2, j = m & 3;
        int b = g / 49, q = g % 49;
        int qy = q / 7, qx = q % 7;
        int py = 2 * qy + (j >> 1), px = 2 * qx + (j & 1);
        grpb[i] = (u32)(((b * 18 + py) * 18 + px) * 2) * 32u + (u32)(lane & 3) * 8u;
    }
    const u16* __restrict__ pp = g_s1p;

    for (int i = tid; i < 2688; i += 256)
        cp16u(sB + (u32)i * 16u, (const char*)g_w2b + (size_t)i * 16);
    cp_commit();

    float d[2][8][4];
#pragma unroll
    for (int mt = 0; mt < 2; mt++)
#pragma unroll
        for (int nt = 0; nt < 8; nt++)
#pragma unroll
            for (int e = 0; e < 4; e++) d[mt][nt][e] = 0.f;

    const u32 lrow = (u32)((lane & 7) + ((lane >> 4) << 3));
    const u32 lkb16 = (u32)(((lane >> 3) & 1) << 4);

    for (int dy = 0; dy < 5; dy++) {
        if (dy < 4) {
            u32 dst = sB + (u32)((dy + 1) & 1) * 43008u;
            const char* src = (const char*)g_w2b + (size_t)(dy + 1) * 43008u;
            for (int i = tid; i < 2688; i += 256)
                cp16u(dst + (u32)i * 16u, src + (size_t)i * 16);
            cp_commit();
            cp_wait1();
        } else {
            cp_wait0();
        }
        __syncthreads();

        const u32 dygrp = (u32)dy * 36u;
        const u32 bb = sB + (u32)(dy & 1) * 43008u;

#pragma unroll
        for (int s = 0; s < 10; s++) {
            const u32 goff = (dygrp + (u32)s) * 32u;
            u32 ah[2][4], al[2][4];
#pragma unroll
            for (int mt = 0; mt < 2; mt++) {
                uint4 q0 = *reinterpret_cast<const uint4*>(pp + grpb[mt * 2] + goff);
                uint4 q1 = *reinterpret_cast<const uint4*>(pp + grpb[mt * 2 + 1] + goff);
                ah[mt][0] = q0.x; al[mt][0] = q0.y; ah[mt][2] = q0.z; al[mt][2] = q0.w;
                ah[mt][1] = q1.x; al[mt][1] = q1.y; ah[mt][3] = q1.z; al[mt][3] = q1.w;
            }
            u32 bh[8][2], bl[8][2];
#pragma unroll
            for (int p = 0; p < 4; p++) {
                u32 ad = bb + ((u32)p * 16u + lrow) * 336u + (u32)s * 32u + lkb16;
                ldsm4(bh[2 * p][0], bh[2 * p][1], bh[2 * p + 1][0], bh[2 * p + 1][1], ad);
                ldsm4(bl[2 * p][0], bl[2 * p][1], bl[2 * p + 1][0], bl[2 * p + 1][1],
                      ad + 21504u);
            }
#pragma unroll
            for (int mt = 0; mt < 2; mt++)
#pragma unroll
                for (int nt = 0; nt < 8; nt++) mma16816(d[mt][nt], ah[mt], bh[nt]);
#pragma unroll
            for (int mt = 0; mt < 2; mt++)
#pragma unroll
                for (int nt = 0; nt < 8; nt++) mma16816(d[mt][nt], al[mt], bh[nt]);
#pragma unroll
            for (int mt = 0; mt < 2; mt++)
#pragma unroll
                for (int nt = 0; nt < 8; nt++) mma16816(d[mt][nt], ah[mt], bl[nt]);
        }
        __syncthreads();
    }

    // epilogue: quad max-pool + bias + relu -> bf16 hi/lo planes
    float bA[8], bB[8];
#pragma unroll
    for (int nt = 0; nt < 8; nt++) {
        int co = nt * 8 + 2 * (lane & 3);
        bA[nt] = b2[co]; bB[nt] = b2[co + 1];
    }
    bool act = ((lane & 12) == 0);
#pragma unroll
    for (int mt = 0; mt < 2; mt++)
#pragma unroll
        for (int rp = 0; rp < 2; rp++) {
            int G = blockIdx.x * 64 + warp * 8 + mt * 4 + rp * 2 + (lane >> 4);
            int b_ = G / 49, q_ = G % 49;
            size_t obase = (size_t)b_ * 3136 + q_ * 64;
#pragma unroll
            for (int nt = 0; nt < 8; nt++) {
                float v0 = d[mt][nt][2 * rp];
                float v1 = d[mt][nt][2 * rp + 1];
                v0 = fmaxf(v0, __shfl_xor_sync(0xffffffffu, v0, 4));
                v0 = fmaxf(v0, __shfl_xor_sync(0xffffffffu, v0, 8));
                v1 = fmaxf(v1, __shfl_xor_sync(0xffffffffu, v1, 4));
                v1 = fmaxf(v1, __shfl_xor_sync(0xffffffffu, v1, 8));
                if (act) {
                    float ox = fmaxf(v0 + bA[nt], 0.f);
                    float oy = fmaxf(v1 + bB[nt], 0.f);
                    __nv_bfloat16 hx = __float2bfloat16(ox), hy = __float2bfloat16(oy);
                    float lx = ox - __bfloat162float(hx);
                    float ly = oy - __bfloat162float(hy);
                    size_t idx = obase + nt * 8 + 2 * (lane & 3);
                    *reinterpret_cast<u32*>(g_s2h + idx) =
                        (u32)reinterpret_cast<u16&>(hx) | ((u32)reinterpret_cast<u16&>(hy) << 16);
                    *reinterpret_cast<u32*>(g_s2l + idx) = bf16pack2(lx, ly);
                }
            }
        }
}

// ============================================================================
// fc1 split-K via mma.sync (bf16 hi/lo x3): M=2048, N=1024, K=3136.
// CTA 256 thr / 8 warps = M128 x N128; grid 16x8x2 (z = K half) -> 256 CTAs.
// Partials (no bias/relu) -> g_fc1p[z]; fc2 combines.
// ============================================================================
__global__ void __launch_bounds__(256, 2) k_fc1(int dummy) {
    extern __shared__ __align__(16) char smf[];
    const u32 sbase = (u32)__cvta_generic_to_shared(smf);

    const int tid = threadIdx.x;
    const int warp = tid >> 5, lane = tid & 31;
    const int wm = warp >> 1, wn = warp & 1;
    const int bm = blockIdx.x * 128, bn = blockIdx.y * 128;
    const int kz = blockIdx.z * 1568;

    const u32 lrow = (u32)((lane & 7) + ((lane >> 4) << 3));
    const u32 lkb16 = (u32)(((lane >> 3) & 1) << 4);
    const u32 arow16 = (u32)(lane & 15);
    const u32 acb16 = (u32)((lane >> 4) << 4);

    auto load_chunk = [&](int buf, int k0) {
        u32 abase = sbase + (u32)buf * 20480u;
        u32 bbase = sbase + 40960u + (u32)buf * 20480u;
        for (int i = tid; i < 2048; i += 256) {
            int sel = i >> 10;
            int r = i & 1023;
            int plane = r >> 9, rr = r & 511;
            int row = rr >> 2, qh = rr & 3;
            const u16* src;
            u32 dst;
            if (sel == 0) {
                src = (plane ? g_s2l : g_s2h) + (size_t)(bm + row) * 3136 + k0 + qh * 8;
                dst = abase;
            } else {
                src = (plane ? g_fc1wl : g_fc1wh) + (size_t)(bn + row) * 3136 + k0 + qh * 8;
                dst = bbase;
            }
            cp16u(dst + (u32)plane * 10240u + (u32)row * 80u + (u32)qh * 16u, src);
        }
    };

    load_chunk(0, kz);
    cp_commit();

    float d[2][8][4];
#pragma unroll
    for (int mt = 0; mt < 2; mt++)
#pragma unroll
        for (int nt = 0; nt < 8; nt++)
#pragma unroll
            for (int e = 0; e < 4; e++) d[mt][nt][e] = 0.f;

    for (int kt = 0; kt < 49; kt++) {
        if (kt < 48) {
            load_chunk((kt + 1) & 1, kz + (kt + 1) * 32);
            cp_commit();
            cp_wait1();
        } else {
            cp_wait0();
        }
        __syncthreads();

        const u32 abuf = sbase + (u32)(kt & 1) * 20480u;
        const u32 bbuf = sbase + 40960u + (u32)(kt & 1) * 20480u;

#pragma unroll
        for (int ks = 0; ks < 2; ks++) {
            u32 ah[2][4], al[2][4];
#pragma unroll
            for (int mt = 0; mt < 2; mt++) {
                u32 ar = abuf + ((u32)(wm * 32 + mt * 16) + arow16) * 80u
                       + (u32)ks * 32u + acb16;
                ldsm4(ah[mt][0], ah[mt][1], ah[mt][2], ah[mt][3], ar);
                ldsm4(al[mt][0], al[mt][1], al[mt][2], al[mt][3], ar + 10240u);
            }
            u32 bh[8][2], bl[8][2];
#pragma unroll
            for (int p = 0; p < 4; p++) {
                u32 ad = bbuf + ((u32)(wn * 64 + p * 16) + lrow) * 80u
                       + (u32)ks * 32u + lkb16;
                ldsm4(bh[2 * p][0], bh[2 * p][1], bh[2 * p + 1][0], bh[2 * p + 1][1], ad);
                ldsm4(bl[2 * p][0], bl[2 * p][1], bl[2 * p + 1][0], bl[2 * p + 1][1],
                      ad + 10240u);
            }
#pragma unroll
            for (int mt = 0; mt < 2; mt++)
#pragma unroll
                for (int nt = 0; nt < 8; nt++) mma16816(d[mt][nt], ah[mt], bh[nt]);
#pragma unroll
            for (int mt = 0; mt < 2; mt++)
#pragma unroll
                for (int nt = 0; nt < 8; nt++) mma16816(d[mt][nt], al[mt], bh[nt]);
#pragma unroll
            for (int mt = 0; mt < 2; mt++)
#pragma unroll
                for (int nt = 0; nt < 8; nt++) mma16816(d[mt][nt], ah[mt], bl[nt]);
        }
        __syncthreads();
    }

    float* outp = g_fc1p + (size_t)blockIdx.z * (2048 * 1024);
#pragma unroll
    for (int nt = 0; nt < 8; nt++) {
        int col = bn + wn * 64 + nt * 8 + (lane & 3) * 2;
#pragma unroll
        for (int mt = 0; mt < 2; mt++)
#pragma unroll
            for (int rp = 0; rp < 2; rp++) {
                int row = bm + wm * 32 + mt * 16 + (lane >> 2) + rp * 8;
                float2 o;
                o.x = d[mt][nt][2 * rp];
                o.y = d[mt][nt][2 * rp + 1];
                *reinterpret_cast<float2*>(&outp[(size_t)row * 1024 + col]) = o;
            }
    }
}

// ============================================================================
// fc2 fused: a = relu(p0 + p1 + b1), out = a @ fc2_w^T + b2. Warp per row.
// ============================================================================
__global__ void __launch_bounds__(256) k_fc2(const float* __restrict__ w,
                                             const float* __restrict__ b1,
                                             const float* __restrict__ b2,
                                             float* __restrict__ out) {
    __shared__ float sb1[1024];
    for (int i = threadIdx.x; i < 1024; i += 256) sb1[i] = b1[i];
    __syncthreads();

    int warp = threadIdx.x >> 5, lane = threadIdx.x & 31;
    int row = blockIdx.x * 8 + warp;
    const float* p0 = g_fc1p + (size_t)row * 1024;
    const float* p1 = g_fc1p + 2048 * 1024 + (size_t)row * 1024;
    float acc[10];
#pragma unroll
    for (int n = 0; n < 10; n++) acc[n] = 0.f;
    for (int k = lane; k < 1024; k += 32) {
        float av = fmaxf(p0[k] + p1[k] + sb1[k], 0.f);
#pragma unroll
        for (int n = 0; n < 10; n++) acc[n] += av * w[n * 1024 + k];
    }
#pragma unroll
    for (int n = 0; n < 10; n++)
#pragma unroll
        for (int off = 16; off > 0; off >>= 1)
            acc[n] += __shfl_xor_sync(0xffffffffu, acc[n], off);
    if (lane == 0) {
#pragma unroll
        for (int n = 0; n < 10; n++) out[row * 10 + n] = acc[n] + b2[n];
    }
}

// ============================================================================
extern "C" void kernel_launch(void* const* d_in, const int* in_sizes, int n_in,
                              void* d_out, int out_size) {
    const float* x       = (const float*)d_in[0];
    const float* conv1_w = (const float*)d_in[1];
    const float* trelu_t = (const float*)d_in[2];
    const float* conv2_w = (const float*)d_in[3];
    const float* conv2_b = (const float*)d_in[4];
    const float* fc1_w   = (const float*)d_in[5];
    const float* fc1_b   = (const float*)d_in[6];
    const float* fc2_w   = (const float*)d_in[7];
    const float* fc2_b   = (const float*)d_in[8];
    float* out = (float*)d_out;

    const int SMEM2 = 2 * 43008;
    const int SMEMF = 2 * 40960;
    cudaFuncSetAttribute(k_conv2, cudaFuncAttributeMaxDynamicSharedMemorySize, SMEM2);
    cudaFuncSetAttribute(k_fc1, cudaFuncAttributeMaxDynamicSharedMemorySize, SMEMF);

    k_prep<<<1024 + 420, 256>>>(conv2_w, fc1_w);
    k_conv1<<<2048, 784>>>(x, conv1_w, trelu_t);
    k_conv2<<<1568, 256, SMEM2>>>(conv2_b);
    k_fc1<<<dim3(16, 8, 2), 256, SMEMF>>>(0);
    k_fc2<<<256, 256>>>(fc2_w, fc1_b, fc2_b, out);
}

// round 14
// speedup vs baseline: 1.0004x; 1.0004x over previous
#include <cuda_runtime.h>
#include <cuda_bf16.h>
#include <cstdint>

typedef unsigned long long ull;
typedef unsigned short u16;
typedef unsigned int u32;

// ---------------- device scratch (static, zero-initialized) ----------------
__device__ __align__(16) u16   g_s1p[2048 * 18 * 18 * 2 * 32]; // conv1 out packed, halo 0
__device__ __align__(16) u16   g_s2h[2048 * 3136];          // conv2 out bf16 hi [b][q*64+co]
__device__ __align__(16) u16   g_s2l[2048 * 3136];          // conv2 out bf16 lo
__device__ __align__(16) float g_fc1p[2 * 2048 * 1024];     // fc1 split-K partials
__device__ __align__(16) u16   g_fc1wh[1024 * 3136];        // fc1 w bf16 hi, K (q,co)
__device__ __align__(16) u16   g_fc1wl[1024 * 3136];        // fc1 w bf16 lo
__device__ __align__(16) u16   g_w2b[5 * 2 * 64 * 168];     // conv2 B [dy][plane][n][k pad 168]

// ---------------- f32x2 helpers ----------------
__device__ __forceinline__ ull ffma2(ull a, ull b, ull c) {
    ull d; asm("fma.rn.f32x2 %0, %1, %2, %3;" : "=l"(d) : "l"(a), "l"(b), "l"(c)); return d;
}
__device__ __forceinline__ ull dup2(float v) {
    ull d; asm("mov.b64 %0, {%1, %1};" : "=l"(d) : "f"(v)); return d;
}
__device__ __forceinline__ ull pk2(float lo, float hi) {
    ull d; asm("mov.b64 %0, {%1, %2};" : "=l"(d) : "f"(lo), "f"(hi)); return d;
}
__device__ __forceinline__ void upk2(ull v, float& lo, float& hi) {
    asm("mov.b64 {%0, %1}, %2;" : "=f"(lo), "=f"(hi) : "l"(v));
}

// ---------------- cp.async (.cg = bypass L1, stream via L2) ----------------
__device__ __forceinline__ void cp16u(u32 saddr, const void* g) {
    asm volatile("cp.async.cg.shared.global [%0], [%1], 16;" :: "r"(saddr), "l"(g));
}
__device__ __forceinline__ void cp_commit() { asm volatile("cp.async.commit_group;"); }
__device__ __forceinline__ void cp_wait0()  { asm volatile("cp.async.wait_group 0;"); }

// ---------------- mma.sync / ldmatrix ----------------
__device__ __forceinline__ void ldsm4(u32& r0, u32& r1, u32& r2, u32& r3, u32 addr) {
    asm volatile("ldmatrix.sync.aligned.m8n8.x4.shared.b16 {%0,%1,%2,%3}, [%4];"
                 : "=r"(r0), "=r"(r1), "=r"(r2), "=r"(r3) : "r"(addr));
}
__device__ __forceinline__ void mma16816(float* d, const u32* a, const u32* b) {
    asm volatile("mma.sync.aligned.m16n8k16.row.col.f32.bf16.bf16.f32 "
                 "{%0,%1,%2,%3}, {%4,%5,%6,%7}, {%8,%9}, {%0,%1,%2,%3};"
                 : "+f"(d[0]), "+f"(d[1]), "+f"(d[2]), "+f"(d[3])
                 : "r"(a[0]), "r"(a[1]), "r"(a[2]), "r"(a[3]), "r"(b[0]), "r"(b[1]));
}

__device__ __forceinline__ void ins4(float& a, float& b, float& c, float& d, float v) {
    if (v > d) {
        d = v;
        if (d > c) { float t = c; c = d; d = t;
            if (c > b) { t = b; b = c; c = t;
                if (b > a) { t = a; a = b; b = t; }
            }
        }
    }
}
__device__ __forceinline__ u32 bf16pack2(float x, float y) {
    __nv_bfloat16 hx = __float2bfloat16(x), hy = __float2bfloat16(y);
    return (u32)reinterpret_cast<u16&>(hx) | ((u32)reinterpret_cast<u16&>(hy) << 16);
}

// ============================================================================
// merged prep: blocks [0,1024) = fc1 weight permute+split; blocks [1024,1444)
// = conv2 B image build.
// ============================================================================
__global__ void __launch_bounds__(256) k_prep(const float* __restrict__ w2,
                                              const float* __restrict__ wfc) {
    __shared__ float row[3136];
    if (blockIdx.x < 1024) {
        int n = blockIdx.x;
        for (int i = threadIdx.x; i < 3136; i += 256) row[i] = wfc[n * 3136 + i];
        __syncthreads();
        for (int i = threadIdx.x; i < 3136; i += 256) {
            int q = i >> 6, co = i & 63;
            float v = row[co * 49 + q];
            __nv_bfloat16 h = __float2bfloat16(v);
            __nv_bfloat16 l2 = __float2bfloat16(v - __bfloat162float(h));
            g_fc1wh[n * 3136 + i] = reinterpret_cast<u16&>(h);
            g_fc1wl[n * 3136 + i] = reinterpret_cast<u16&>(l2);
        }
    } else {
        int i = (blockIdx.x - 1024) * 256 + threadIdx.x;
        if (i >= 5 * 2 * 64 * 168) return;
        int dy = i / 21504, r = i % 21504;
        int plane = r / 10752, r2 = r % 10752;
        int co = r2 / 168, k = r2 % 168;
        float v = 0.f;
        if (k < 160) {
            int dx = k >> 5, ci = k & 31;
            v = w2[(co * 32 + ci) * 25 + dy * 5 + dx];
        }
        __nv_bfloat16 h = __float2bfloat16(v);
        if (plane == 0) {
            g_w2b[i] = reinterpret_cast<u16&>(h);
        } else {
            __nv_bfloat16 l2 = __float2bfloat16(v - __bfloat162float(h));
            g_w2b[i] = reinterpret_cast<u16&>(l2);
        }
    }
}

// ============================================================================
// conv1 (1->32, 5x5, pad2) + top-4 mask + threshold ReLU + 2x2 maxpool.
// SINGLE pass: CTA = 784 threads = 1 image, thread = 1 pixel (quad-major).
// ============================================================================
__global__ void __launch_bounds__(784) k_conv1(const float* __restrict__ xin,
                                               const float* __restrict__ w1,
                                               const float* __restrict__ tt) {
    __shared__ float s_img[1024];
    __shared__ ull   s_wp[400];
    __shared__ float s_t[32];

    const int tid = threadIdx.x;
    const int img = blockIdx.x;

    for (int i = tid; i < 1024; i += 784) s_img[i] = 0.f;
    for (int i = tid; i < 400; i += 784) {
        int tap = i >> 4, c16 = i & 15;
        s_wp[i] = pk2(w1[(2 * c16) * 25 + tap], w1[(2 * c16 + 1) * 25 + tap]);
    }
    if (tid < 32) s_t[tid] = tt[tid];
    __syncthreads();
    {
        int y = tid / 28, xx = tid % 28;
        s_img[(y + 2) * 32 + xx + 2] = xin[img * 784 + tid];
    }
    __syncthreads();

    const int q = tid >> 2, j = tid & 3;
    const int PY = q / 14, PX = q % 14;
    const int py = 2 * PY + (j >> 1), px = 2 * PX + (j & 1);
    const float* base = &s_img[py * 32 + px];

    ull acc[16];
#pragma unroll
    for (int c = 0; c < 16; c++) acc[c] = 0ull;
#pragma unroll
    for (int dy = 0; dy < 5; dy++)
#pragma unroll
        for (int dx = 0; dx < 5; dx++) {
            ull wd = dup2(base[dy * 32 + dx]);
            const ull* wp = &s_wp[(dy * 5 + dx) * 16];
#pragma unroll
            for (int c = 0; c < 16; c++) acc[c] = ffma2(wd, wp[c], acc[c]);
        }

    float vals[32];
#pragma unroll
    for (int c = 0; c < 16; c++) upk2(acc[c], vals[2 * c], vals[2 * c + 1]);

    float a4 = -3.4e38f, b4 = -3.4e38f, c4 = -3.4e38f, d4 = -3.4e38f;
#pragma unroll
    for (int c = 0; c < 32; c++) ins4(a4, b4, c4, d4, vals[c]);

    const u32 lane = (u32)(tid & 31);
    const u32 qm = 0xFu << (lane & ~3u);
#pragma unroll
    for (int c = 0; c < 32; c++) {
        float v = vals[c];
        float r = (v >= d4) ? fmaxf(v - s_t[c], 0.f) : 0.f;
        r = fmaxf(r, __shfl_xor_sync(qm, r, 1));
        r = fmaxf(r, __shfl_xor_sync(qm, r, 2));
        vals[c] = r;
    }

    if (j == 0) {
        u16 oh[32], ol[32];
#pragma unroll
        for (int c = 0; c < 32; c++) {
            float v = vals[c];
            __nv_bfloat16 h = __float2bfloat16(v);
            oh[c] = reinterpret_cast<u16&>(h);
            __nv_bfloat16 l2 = __float2bfloat16(v - __bfloat162float(h));
            ol[c] = reinterpret_cast<u16&>(l2);
        }
        size_t gb = ((((size_t)img * 18 + (PY + 2)) * 18 + (PX + 2)) * 2) * 32;
#pragma unroll
        for (int g = 0; g < 2; g++) {
#pragma unroll
            for (int c = 0; c < 4; c++) {
                __align__(16) u16 buf[8];
                buf[0] = oh[g * 16 + 2 * c];     buf[1] = oh[g * 16 + 2 * c + 1];
                buf[2] = ol[g * 16 + 2 * c];     buf[3] = ol[g * 16 + 2 * c + 1];
                buf[4] = oh[g * 16 + 2 * c + 8]; buf[5] = oh[g * 16 + 2 * c + 9];
                buf[6] = ol[g * 16 + 2 * c + 8]; buf[7] = ol[g * 16 + 2 * c + 9];
                *reinterpret_cast<uint4*>(g_s1p + gb + g * 32 + c * 8) =
                    *reinterpret_cast<uint4*>(buf);
            }
        }
    }
}

// ============================================================================
// conv2 via mma.sync (bf16 hi/lo x3): 5 accumulated GEMMs, K=160 per dy.
// CTA = 256 threads / 8 warps, M=256 rows; warp = m32 x n64, 2 CTAs/SM.
// Prefetch issued AFTER the barrier (race-free: barrier guarantees all warps
// finished reading the buffer being overwritten).
// ============================================================================
__global__ void __launch_bounds__(256, 2) k_conv2(const float* __restrict__ b2) {
    extern __shared__ __align__(16) char sm2[];
    u32 sB = (u32)__cvta_generic_to_shared(sm2);   // 2 x 43008 B buffers

    const int tid = threadIdx.x;
    const int warp = tid >> 5, lane = tid & 31;

    u32 grpb[4];
#pragma unroll
    for (int i = 0; i < 4; i++) {
        int r = warp * 32 + ((i & 1) << 3) + ((i >> 1) << 4) + (lane >> 2);
        int m = blockIdx.x * 256 + r;
        int g = m >> 2, j = m & 3;
        int b = g / 49, q = g % 49;
        int qy = q / 7, qx = q % 7;
        int py = 2 * qy + (j >> 1), px = 2 * qx + (j & 1);
        grpb[i] = (u32)(((b * 18 + py) * 18 + px) * 2) * 32u + (u32)(lane & 3) * 8u;
    }
    const u16* __restrict__ pp = g_s1p;

    for (int i = tid; i < 2688; i += 256)
        cp16u(sB + (u32)i * 16u, (const char*)g_w2b + (size_t)i * 16);
    cp_commit();

    float d[2][8][4];
#pragma unroll
    for (int mt = 0; mt < 2; mt++)
#pragma unroll
        for (int nt = 0; nt < 8; nt++)
#pragma unroll
            for (int e = 0; e < 4; e++) d[mt][nt][e] = 0.f;

    const u32 lrow = (u32)((lane & 7) + ((lane >> 4) << 3));
    const u32 lkb16 = (u32)(((lane >> 3) & 1) << 4);

    for (int dy = 0; dy < 5; dy++) {
        cp_wait0();          // chunk dy resident
        __syncthreads();     // all warps done with the other buffer
        if (dy < 4) {        // prefetch dy+1 (lands during compute of dy)
            u32 dst = sB + (u32)((dy + 1) & 1) * 43008u;
            const char* src = (const char*)g_w2b + (size_t)(dy + 1) * 43008u;
            for (int i = tid; i < 2688; i += 256)
                cp16u(dst + (u32)i * 16u, src + (size_t)i * 16);
            cp_commit();
        }

        const u32 dygrp = (u32)dy * 36u;
        const u32 bb = sB + (u32)(dy & 1) * 43008u;

#pragma unroll
        for (int s = 0; s < 10; s++) {
            const u32 goff = (dygrp + (u32)s) * 32u;
            u32 ah[2][4], al[2][4];
#pragma unroll
            for (int mt = 0; mt < 2; mt++) {
                uint4 q0 = *reinterpret_cast<const uint4*>(pp + grpb[mt * 2] + goff);
                uint4 q1 = *reinterpret_cast<const uint4*>(pp + grpb[mt * 2 + 1] + goff);
                ah[mt][0] = q0.x; al[mt][0] = q0.y; ah[mt][2] = q0.z; al[mt][2] = q0.w;
                ah[mt][1] = q1.x; al[mt][1] = q1.y; ah[mt][3] = q1.z; al[mt][3] = q1.w;
            }
            u32 bh[8][2], bl[8][2];
#pragma unroll
            for (int p = 0; p < 4; p++) {
                u32 ad = bb + ((u32)p * 16u + lrow) * 336u + (u32)s * 32u + lkb16;
                ldsm4(bh[2 * p][0], bh[2 * p][1], bh[2 * p + 1][0], bh[2 * p + 1][1], ad);
                ldsm4(bl[2 * p][0], bl[2 * p][1], bl[2 * p + 1][0], bl[2 * p + 1][1],
                      ad + 21504u);
            }
#pragma unroll
            for (int mt = 0; mt < 2; mt++)
#pragma unroll
                for (int nt = 0; nt < 8; nt++) mma16816(d[mt][nt], ah[mt], bh[nt]);
#pragma unroll
            for (int mt = 0; mt < 2; mt++)
#pragma unroll
                for (int nt = 0; nt < 8; nt++) mma16816(d[mt][nt], al[mt], bh[nt]);
#pragma unroll
            for (int mt = 0; mt < 2; mt++)
#pragma unroll
                for (int nt = 0; nt < 8; nt++) mma16816(d[mt][nt], ah[mt], bl[nt]);
        }
    }

    // epilogue: quad max-pool + bias + relu -> bf16 hi/lo planes
    float bA[8], bB[8];
#pragma unroll
    for (int nt = 0; nt < 8; nt++) {
        int co = nt * 8 + 2 * (lane & 3);
        bA[nt] = b2[co]; bB[nt] = b2[co + 1];
    }
    bool act = ((lane & 12) == 0);
#pragma unroll
    for (int mt = 0; mt < 2; mt++)
#pragma unroll
        for (int rp = 0; rp < 2; rp++) {
            int G = blockIdx.x * 64 + warp * 8 + mt * 4 + rp * 2 + (lane >> 4);
            int b_ = G / 49, q_ = G % 49;
            size_t obase = (size_t)b_ * 3136 + q_ * 64;
#pragma unroll
            for (int nt = 0; nt < 8; nt++) {
                float v0 = d[mt][nt][2 * rp];
                float v1 = d[mt][nt][2 * rp + 1];
                v0 = fmaxf(v0, __shfl_xor_sync(0xffffffffu, v0, 4));
                v0 = fmaxf(v0, __shfl_xor_sync(0xffffffffu, v0, 8));
                v1 = fmaxf(v1, __shfl_xor_sync(0xffffffffu, v1, 4));
                v1 = fmaxf(v1, __shfl_xor_sync(0xffffffffu, v1, 8));
                if (act) {
                    float ox = fmaxf(v0 + bA[nt], 0.f);
                    float oy = fmaxf(v1 + bB[nt], 0.f);
                    __nv_bfloat16 hx = __float2bfloat16(ox), hy = __float2bfloat16(oy);
                    float lx = ox - __bfloat162float(hx);
                    float ly = oy - __bfloat162float(hy);
                    size_t idx = obase + nt * 8 + 2 * (lane & 3);
                    *reinterpret_cast<u32*>(g_s2h + idx) =
                        (u32)reinterpret_cast<u16&>(hx) | ((u32)reinterpret_cast<u16&>(hy) << 16);
                    *reinterpret_cast<u32*>(g_s2l + idx) = bf16pack2(lx, ly);
                }
            }
        }
}

// ============================================================================
// fc1 split-K via mma.sync (bf16 hi/lo x3): M=2048, N=1024, K=3136.
// CTA 256 thr / 8 warps = M128 x N128; grid 16x8x2 (z = K half) -> 256 CTAs.
// Race-free prefetch-after-barrier ordering. Partials -> g_fc1p[z].
// ============================================================================
__global__ void __launch_bounds__(256, 2) k_fc1(int dummy) {
    extern __shared__ __align__(16) char smf[];
    const u32 sbase = (u32)__cvta_generic_to_shared(smf);

    const int tid = threadIdx.x;
    const int warp = tid >> 5, lane = tid & 31;
    const int wm = warp >> 1, wn = warp & 1;
    const int bm = blockIdx.x * 128, bn = blockIdx.y * 128;
    const int kz = blockIdx.z * 1568;

    const u32 lrow = (u32)((lane & 7) + ((lane >> 4) << 3));
    const u32 lkb16 = (u32)(((lane >> 3) & 1) << 4);
    const u32 arow16 = (u32)(lane & 15);
    const u32 acb16 = (u32)((lane >> 4) << 4);

    auto load_chunk = [&](int buf, int k0) {
        u32 abase = sbase + (u32)buf * 20480u;
        u32 bbase = sbase + 40960u + (u32)buf * 20480u;
        for (int i = tid; i < 2048; i += 256) {
            int sel = i >> 10;
            int r = i & 1023;
            int plane = r >> 9, rr = r & 511;
            int row = rr >> 2, qh = rr & 3;
            const u16* src;
            u32 dst;
            if (sel == 0) {
                src = (plane ? g_s2l : g_s2h) + (size_t)(bm + row) * 3136 + k0 + qh * 8;
                dst = abase;
            } else {
                src = (plane ? g_fc1wl : g_fc1wh) + (size_t)(bn + row) * 3136 + k0 + qh * 8;
                dst = bbase;
            }
            cp16u(dst + (u32)plane * 10240u + (u32)row * 80u + (u32)qh * 16u, src);
        }
    };

    load_chunk(0, kz);
    cp_commit();

    float d[2][8][4];
#pragma unroll
    for (int mt = 0; mt < 2; mt++)
#pragma unroll
        for (int nt = 0; nt < 8; nt++)
#pragma unroll
            for (int e = 0; e < 4; e++) d[mt][nt][e] = 0.f;

    for (int kt = 0; kt < 49; kt++) {
        cp_wait0();          // chunk kt resident
        __syncthreads();     // all warps done reading the other buffer
        if (kt < 48) {       // prefetch kt+1
            load_chunk((kt + 1) & 1, kz + (kt + 1) * 32);
            cp_commit();
        }

        const u32 abuf = sbase + (u32)(kt & 1) * 20480u;
        const u32 bbuf = sbase + 40960u + (u32)(kt & 1) * 20480u;

#pragma unroll
        for (int ks = 0; ks < 2; ks++) {
            u32 ah[2][4], al[2][4];
#pragma unroll
            for (int mt = 0; mt < 2; mt++) {
                u32 ar = abuf + ((u32)(wm * 32 + mt * 16) + arow16) * 80u
                       + (u32)ks * 32u + acb16;
                ldsm4(ah[mt][0], ah[mt][1], ah[mt][2], ah[mt][3], ar);
                ldsm4(al[mt][0], al[mt][1], al[mt][2], al[mt][3], ar + 10240u);
            }
            u32 bh[8][2], bl[8][2];
#pragma unroll
            for (int p = 0; p < 4; p++) {
                u32 ad = bbuf + ((u32)(wn * 64 + p * 16) + lrow) * 80u
                       + (u32)ks * 32u + lkb16;
                ldsm4(bh[2 * p][0], bh[2 * p][1], bh[2 * p + 1][0], bh[2 * p + 1][1], ad);
                ldsm4(bl[2 * p][0], bl[2 * p][1], bl[2 * p + 1][0], bl[2 * p + 1][1],
                      ad + 10240u);
            }
#pragma unroll
            for (int mt = 0; mt < 2; mt++)
#pragma unroll
                for (int nt = 0; nt < 8; nt++) mma16816(d[mt][nt], ah[mt], bh[nt]);
#pragma unroll
            for (int mt = 0; mt < 2; mt++)
#pragma unroll
                for (int nt = 0; nt < 8; nt++) mma16816(d[mt][nt], al[mt], bh[nt]);
#pragma unroll
            for (int mt = 0; mt < 2; mt++)
#pragma unroll
                for (int nt = 0; nt < 8; nt++) mma16816(d[mt][nt], ah[mt], bl[nt]);
        }
    }

    float* outp = g_fc1p + (size_t)blockIdx.z * (2048 * 1024);
#pragma unroll
    for (int nt = 0; nt < 8; nt++) {
        int col = bn + wn * 64 + nt * 8 + (lane & 3) * 2;
#pragma unroll
        for (int mt = 0; mt < 2; mt++)
#pragma unroll
            for (int rp = 0; rp < 2; rp++) {
                int row = bm + wm * 32 + mt * 16 + (lane >> 2) + rp * 8;
                float2 o;
                o.x = d[mt][nt][2 * rp];
                o.y = d[mt][nt][2 * rp + 1];
                *reinterpret_cast<float2*>(&outp[(size_t)row * 1024 + col]) = o;
            }
    }
}

// ============================================================================
// fc2 fused: a = relu(p0 + p1 + b1), out = a @ fc2_w^T + b2. Warp per row.
// ============================================================================
__global__ void __launch_bounds__(256) k_fc2(const float* __restrict__ w,
                                             const float* __restrict__ b1,
                                             const float* __restrict__ b2,
                                             float* __restrict__ out) {
    __shared__ float sb1[1024];
    for (int i = threadIdx.x; i < 1024; i += 256) sb1[i] = b1[i];
    __syncthreads();

    int warp = threadIdx.x >> 5, lane = threadIdx.x & 31;
    int row = blockIdx.x * 8 + warp;
    const float* p0 = g_fc1p + (size_t)row * 1024;
    const float* p1 = g_fc1p + 2048 * 1024 + (size_t)row * 1024;
    float acc[10];
#pragma unroll
    for (int n = 0; n < 10; n++) acc[n] = 0.f;
    for (int k = lane; k < 1024; k += 32) {
        float av = fmaxf(p0[k] + p1[k] + sb1[k], 0.f);
#pragma unroll
        for (int n = 0; n < 10; n++) acc[n] += av * w[n * 1024 + k];
    }
#pragma unroll
    for (int n = 0; n < 10; n++)
#pragma unroll
        for (int off = 16; off > 0; off >>= 1)
            acc[n] += __shfl_xor_sync(0xffffffffu, acc[n], off);
    if (lane == 0) {
#pragma unroll
        for (int n = 0; n < 10; n++) out[row * 10 + n] = acc[n] + b2[n];
    }
}

// ============================================================================
extern "C" void kernel_launch(void* const* d_in, const int* in_sizes, int n_in,
                              void* d_out, int out_size) {
    const float* x       = (const float*)d_in[0];
    const float* conv1_w = (const float*)d_in[1];
    const float* trelu_t = (const float*)d_in[2];
    const float* conv2_w = (const float*)d_in[3];
    const float* conv2_b = (const float*)d_in[4];
    const float* fc1_w   = (const float*)d_in[5];
    const float* fc1_b   = (const float*)d_in[6];
    const float* fc2_w   = (const float*)d_in[7];
    const float* fc2_b   = (const float*)d_in[8];
    float* out = (float*)d_out;

    const int SMEM2 = 2 * 43008;
    const int SMEMF = 2 * 40960;
    cudaFuncSetAttribute(k_conv2, cudaFuncAttributeMaxDynamicSharedMemorySize, SMEM2);
    cudaFuncSetAttribute(k_fc1, cudaFuncAttributeMaxDynamicSharedMemorySize, SMEMF);

    k_prep<<<1024 + 420, 256>>>(conv2_w, fc1_w);
    k_conv1<<<2048, 784>>>(x, conv1_w, trelu_t);
    k_conv2<<<1568, 256, SMEM2>>>(conv2_b);
    k_fc1<<<dim3(16, 8, 2), 256, SMEMF>>>(0);
    k_fc2<<<256, 256>>>(fc2_w, fc1_b, fc2_b, out);
}

// round 15
// speedup vs baseline: 1.0103x; 1.0099x over previous
#include <cuda_runtime.h>
#include <cuda_bf16.h>
#include <cstdint>

typedef unsigned long long ull;
typedef unsigned short u16;
typedef unsigned int u32;

// ---------------- device scratch (static, zero-initialized) ----------------
__device__ __align__(16) u16   g_s1p[2048 * 18 * 18 * 2 * 32]; // conv1 out packed, halo 0
__device__ __align__(16) u16   g_s2h[2048 * 3136];          // conv2 out bf16 hi [b][q*64+co]
__device__ __align__(16) u16   g_s2l[2048 * 3136];          // conv2 out bf16 lo
__device__ __align__(16) float g_fc1p[2 * 2048 * 1024];     // fc1 split-K partials
__device__ __align__(16) u16   g_fc1wh[1024 * 3136];        // fc1 w bf16 hi, K (q,co)
__device__ __align__(16) u16   g_fc1wl[1024 * 3136];        // fc1 w bf16 lo
__device__ __align__(16) u16   g_w2b[5 * 2 * 64 * 168];     // conv2 B [dy][plane][n][k pad 168]

// ---------------- f32x2 helpers ----------------
__device__ __forceinline__ ull ffma2(ull a, ull b, ull c) {
    ull d; asm("fma.rn.f32x2 %0, %1, %2, %3;" : "=l"(d) : "l"(a), "l"(b), "l"(c)); return d;
}
__device__ __forceinline__ ull dup2(float v) {
    ull d; asm("mov.b64 %0, {%1, %1};" : "=l"(d) : "f"(v)); return d;
}
__device__ __forceinline__ ull pk2(float lo, float hi) {
    ull d; asm("mov.b64 %0, {%1, %2};" : "=l"(d) : "f"(lo), "f"(hi)); return d;
}
__device__ __forceinline__ void upk2(ull v, float& lo, float& hi) {
    asm("mov.b64 {%0, %1}, %2;" : "=f"(lo), "=f"(hi) : "l"(v));
}

// ---------------- cp.async (.ca — the empirically faster config) ----------------
__device__ __forceinline__ void cp16u(u32 saddr, const void* g) {
    asm volatile("cp.async.ca.shared.global [%0], [%1], 16;" :: "r"(saddr), "l"(g));
}
__device__ __forceinline__ void cp_commit() { asm volatile("cp.async.commit_group;"); }
__device__ __forceinline__ void cp_wait0()  { asm volatile("cp.async.wait_group 0;"); }
__device__ __forceinline__ void cp_wait1()  { asm volatile("cp.async.wait_group 1;"); }

// ---------------- mma.sync / ldmatrix ----------------
__device__ __forceinline__ void ldsm4(u32& r0, u32& r1, u32& r2, u32& r3, u32 addr) {
    asm volatile("ldmatrix.sync.aligned.m8n8.x4.shared.b16 {%0,%1,%2,%3}, [%4];"
                 : "=r"(r0), "=r"(r1), "=r"(r2), "=r"(r3) : "r"(addr));
}
__device__ __forceinline__ void mma16816(float* d, const u32* a, const u32* b) {
    asm volatile("mma.sync.aligned.m16n8k16.row.col.f32.bf16.bf16.f32 "
                 "{%0,%1,%2,%3}, {%4,%5,%6,%7}, {%8,%9}, {%0,%1,%2,%3};"
                 : "+f"(d[0]), "+f"(d[1]), "+f"(d[2]), "+f"(d[3])
                 : "r"(a[0]), "r"(a[1]), "r"(a[2]), "r"(a[3]), "r"(b[0]), "r"(b[1]));
}

__device__ __forceinline__ void ins4(float& a, float& b, float& c, float& d, float v) {
    if (v > d) {
        d = v;
        if (d > c) { float t = c; c = d; d = t;
            if (c > b) { t = b; b = c; c = t;
                if (b > a) { t = a; a = b; b = t; }
            }
        }
    }
}
__device__ __forceinline__ u32 bf16pack2(float x, float y) {
    __nv_bfloat16 hx = __float2bfloat16(x), hy = __float2bfloat16(y);
    return (u32)reinterpret_cast<u16&>(hx) | ((u32)reinterpret_cast<u16&>(hy) << 16);
}

// ============================================================================
// conv1 + prep, fused as block ranges of one kernel (overlap in one wave):
//  blocks [0,2048)        : conv1 (1->32, 5x5, pad2) + top-4 + trelu + pool
//  blocks [2048,3072)     : fc1 weight permute + bf16 hi/lo split
//  blocks [3072,3210)     : conv2 B image build
// ============================================================================
__global__ void __launch_bounds__(784) k_conv1(const float* __restrict__ xin,
                                               const float* __restrict__ w1,
                                               const float* __restrict__ tt,
                                               const float* __restrict__ w2,
                                               const float* __restrict__ wfc) {
    __shared__ float s_img[1024];
    __shared__ ull   s_wp[400];
    __shared__ float s_t[32];

    const int tid = threadIdx.x;
    const int bid = blockIdx.x;

    if (bid >= 2048) {
        if (bid < 3072) {
            // fc1 weight permute (k = co*49+q -> j = q*64+co) + hi/lo split
            float* row = s_img;  // reuse smem (needs 3136 floats; s_img+s_wp+s_t
                                 // = 1024+800+32... not enough). Use global read twice:
            int n = bid - 2048;
            for (int i = tid; i < 3136; i += 784) {
                int q = i >> 6, co = i & 63;
                float v = wfc[n * 3136 + co * 49 + q];
                __nv_bfloat16 h = __float2bfloat16(v);
                __nv_bfloat16 l2 = __float2bfloat16(v - __bfloat162float(h));
                g_fc1wh[n * 3136 + i] = reinterpret_cast<u16&>(h);
                g_fc1wl[n * 3136 + i] = reinterpret_cast<u16&>(l2);
            }
            (void)row;
        } else {
            // conv2 B image build
            int i = (bid - 3072) * 784 + tid;
            if (i < 5 * 2 * 64 * 168) {
                int dy = i / 21504, r = i % 21504;
                int plane = r / 10752, r2 = r % 10752;
                int co = r2 / 168, k = r2 % 168;
                float v = 0.f;
                if (k < 160) {
                    int dx = k >> 5, ci = k & 31;
                    v = w2[(co * 32 + ci) * 25 + dy * 5 + dx];
                }
                __nv_bfloat16 h = __float2bfloat16(v);
                if (plane == 0) {
                    g_w2b[i] = reinterpret_cast<u16&>(h);
                } else {
                    __nv_bfloat16 l2 = __float2bfloat16(v - __bfloat162float(h));
                    g_w2b[i] = reinterpret_cast<u16&>(l2);
                }
            }
        }
        return;
    }

    const int img = bid;

    for (int i = tid; i < 1024; i += 784) s_img[i] = 0.f;
    for (int i = tid; i < 400; i += 784) {
        int tap = i >> 4, c16 = i & 15;
        s_wp[i] = pk2(w1[(2 * c16) * 25 + tap], w1[(2 * c16 + 1) * 25 + tap]);
    }
    if (tid < 32) s_t[tid] = tt[tid];
    __syncthreads();
    {
        int y = tid / 28, xx = tid % 28;
        s_img[(y + 2) * 32 + xx + 2] = xin[img * 784 + tid];
    }
    __syncthreads();

    const int q = tid >> 2, j = tid & 3;
    const int PY = q / 14, PX = q % 14;
    const int py = 2 * PY + (j >> 1), px = 2 * PX + (j & 1);
    const float* base = &s_img[py * 32 + px];

    ull acc[16];
#pragma unroll
    for (int c = 0; c < 16; c++) acc[c] = 0ull;
#pragma unroll
    for (int dy = 0; dy < 5; dy++)
#pragma unroll
        for (int dx = 0; dx < 5; dx++) {
            ull wd = dup2(base[dy * 32 + dx]);
            const ull* wp = &s_wp[(dy * 5 + dx) * 16];
#pragma unroll
            for (int c = 0; c < 16; c++) acc[c] = ffma2(wd, wp[c], acc[c]);
        }

    float vals[32];
#pragma unroll
    for (int c = 0; c < 16; c++) upk2(acc[c], vals[2 * c], vals[2 * c + 1]);

    float a4 = -3.4e38f, b4 = -3.4e38f, c4 = -3.4e38f, d4 = -3.4e38f;
#pragma unroll
    for (int c = 0; c < 32; c++) ins4(a4, b4, c4, d4, vals[c]);

    const u32 lane = (u32)(tid & 31);
    const u32 qm = 0xFu << (lane & ~3u);
#pragma unroll
    for (int c = 0; c < 32; c++) {
        float v = vals[c];
        float r = (v >= d4) ? fmaxf(v - s_t[c], 0.f) : 0.f;
        r = fmaxf(r, __shfl_xor_sync(qm, r, 1));
        r = fmaxf(r, __shfl_xor_sync(qm, r, 2));
        vals[c] = r;
    }

    if (j == 0) {
        u16 oh[32], ol[32];
#pragma unroll
        for (int c = 0; c < 32; c++) {
            float v = vals[c];
            __nv_bfloat16 h = __float2bfloat16(v);
            oh[c] = reinterpret_cast<u16&>(h);
            __nv_bfloat16 l2 = __float2bfloat16(v - __bfloat162float(h));
            ol[c] = reinterpret_cast<u16&>(l2);
        }
        size_t gb = ((((size_t)img * 18 + (PY + 2)) * 18 + (PX + 2)) * 2) * 32;
#pragma unroll
        for (int g = 0; g < 2; g++) {
#pragma unroll
            for (int c = 0; c < 4; c++) {
                __align__(16) u16 buf[8];
                buf[0] = oh[g * 16 + 2 * c];     buf[1] = oh[g * 16 + 2 * c + 1];
                buf[2] = ol[g * 16 + 2 * c];     buf[3] = ol[g * 16 + 2 * c + 1];
                buf[4] = oh[g * 16 + 2 * c + 8]; buf[5] = oh[g * 16 + 2 * c + 9];
                buf[6] = ol[g * 16 + 2 * c + 8]; buf[7] = ol[g * 16 + 2 * c + 9];
                *reinterpret_cast<uint4*>(g_s1p + gb + g * 32 + c * 8) =
                    *reinterpret_cast<uint4*>(buf);
            }
        }
    }
}

// ============================================================================
// conv2 via mma.sync (bf16 hi/lo x3): 5 accumulated GEMMs, K=160 per dy.
// CTA = 256 threads / 8 warps, M=256 rows; warp = m32 x n64, 2 CTAs/SM.
// (R13-measured pipeline: early prefetch + wait_group 1.)
// ============================================================================
__global__ void __launch_bounds__(256, 2) k_conv2(const float* __restrict__ b2) {
    extern __shared__ __align__(16) char sm2[];
    u32 sB = (u32)__cvta_generic_to_shared(sm2);   // 2 x 43008 B buffers

    const int tid = threadIdx.x;
    const int warp = tid >> 5, lane = tid & 31;

    u32 grpb[4];
#pragma unroll
    for (int i = 0; i < 4; i++) {
        int r = warp * 32 + ((i & 1) << 3) + ((i >> 1) << 4) + (lane >> 2);
        int m = blockIdx.x * 256 + r;
        int g = m >> 2, j = m & 3;
        int b = g / 49, q = g % 49;
        int qy = q / 7, qx = q % 7;
        int py = 2 * qy + (j >> 1), px = 2 * qx + (j & 1);
        grpb[i] = (u32)(((b * 18 + py) * 18 + px) * 2) * 32u + (u32)(lane & 3) * 8u;
    }
    const u16* __restrict__ pp = g_s1p;

    for (int i = tid; i < 2688; i += 256)
        cp16u(sB + (u32)i * 16u, (const char*)g_w2b + (size_t)i * 16);
    cp_commit();

    float d[2][8][4];
#pragma unroll
    for (int mt = 0; mt < 2; mt++)
#pragma unroll
        for (int nt = 0; nt < 8; nt++)
#pragma unroll
            for (int e = 0; e < 4; e++) d[mt][nt][e] = 0.f;

    const u32 lrow = (u32)((lane & 7) + ((lane >> 4) << 3));
    const u32 lkb16 = (u32)(((lane >> 3) & 1) << 4);

    for (int dy = 0; dy < 5; dy++) {
        if (dy < 4) {
            u32 dst = sB + (u32)((dy + 1) & 1) * 43008u;
            const char* src = (const char*)g_w2b + (size_t)(dy + 1) * 43008u;
            for (int i = tid; i < 2688; i += 256)
                cp16u(dst + (u32)i * 16u, src + (size_t)i * 16);
            cp_commit();
            cp_wait1();
        } else {
            cp_wait0();
        }
        __syncthreads();

        const u32 dygrp = (u32)dy * 36u;
        const u32 bb = sB + (u32)(dy & 1) * 43008u;

#pragma unroll
        for (int s = 0; s < 10; s++) {
            const u32 goff = (dygrp + (u32)s) * 32u;
            u32 ah[2][4], al[2][4];
#pragma unroll
            for (int mt = 0; mt < 2; mt++) {
                uint4 q0 = *reinterpret_cast<const uint4*>(pp + grpb[mt * 2] + goff);
                uint4 q1 = *reinterpret_cast<const uint4*>(pp + grpb[mt * 2 + 1] + goff);
                ah[mt][0] = q0.x; al[mt][0] = q0.y; ah[mt][2] = q0.z; al[mt][2] = q0.w;
                ah[mt][1] = q1.x; al[mt][1] = q1.y; ah[mt][3] = q1.z; al[mt][3] = q1.w;
            }
            u32 bh[8][2], bl[8][2];
#pragma unroll
            for (int p = 0; p < 4; p++) {
                u32 ad = bb + ((u32)p * 16u + lrow) * 336u + (u32)s * 32u + lkb16;
                ldsm4(bh[2 * p][0], bh[2 * p][1], bh[2 * p + 1][0], bh[2 * p + 1][1], ad);
                ldsm4(bl[2 * p][0], bl[2 * p][1], bl[2 * p + 1][0], bl[2 * p + 1][1],
                      ad + 21504u);
            }
#pragma unroll
            for (int mt = 0; mt < 2; mt++)
#pragma unroll
                for (int nt = 0; nt < 8; nt++) mma16816(d[mt][nt], ah[mt], bh[nt]);
#pragma unroll
            for (int mt = 0; mt < 2; mt++)
#pragma unroll
                for (int nt = 0; nt < 8; nt++) mma16816(d[mt][nt], al[mt], bh[nt]);
#pragma unroll
            for (int mt = 0; mt < 2; mt++)
#pragma unroll
                for (int nt = 0; nt < 8; nt++) mma16816(d[mt][nt], ah[mt], bl[nt]);
        }
        __syncthreads();
    }

    // epilogue: quad max-pool + bias + relu -> bf16 hi/lo planes
    float bA[8], bB[8];
#pragma unroll
    for (int nt = 0; nt < 8; nt++) {
        int co = nt * 8 + 2 * (lane & 3);
        bA[nt] = b2[co]; bB[nt] = b2[co + 1];
    }
    bool act = ((lane & 12) == 0);
#pragma unroll
    for (int mt = 0; mt < 2; mt++)
#pragma unroll
        for (int rp = 0; rp < 2; rp++) {
            int G = blockIdx.x * 64 + warp * 8 + mt * 4 + rp * 2 + (lane >> 4);
            int b_ = G / 49, q_ = G % 49;
            size_t obase = (size_t)b_ * 3136 + q_ * 64;
#pragma unroll
            for (int nt = 0; nt < 8; nt++) {
                float v0 = d[mt][nt][2 * rp];
                float v1 = d[mt][nt][2 * rp + 1];
                v0 = fmaxf(v0, __shfl_xor_sync(0xffffffffu, v0, 4));
                v0 = fmaxf(v0, __shfl_xor_sync(0xffffffffu, v0, 8));
                v1 = fmaxf(v1, __shfl_xor_sync(0xffffffffu, v1, 4));
                v1 = fmaxf(v1, __shfl_xor_sync(0xffffffffu, v1, 8));
                if (act) {
                    float ox = fmaxf(v0 + bA[nt], 0.f);
                    float oy = fmaxf(v1 + bB[nt], 0.f);
                    __nv_bfloat16 hx = __float2bfloat16(ox), hy = __float2bfloat16(oy);
                    float lx = ox - __bfloat162float(hx);
                    float ly = oy - __bfloat162float(hy);
                    size_t idx = obase + nt * 8 + 2 * (lane & 3);
                    *reinterpret_cast<u32*>(g_s2h + idx) =
                        (u32)reinterpret_cast<u16&>(hx) | ((u32)reinterpret_cast<u16&>(hy) << 16);
                    *reinterpret_cast<u32*>(g_s2l + idx) = bf16pack2(lx, ly);
                }
            }
        }
}

// ============================================================================
// fc1 split-K via mma.sync (bf16 hi/lo x3): M=2048, N=1024, K=3136.
// CTA 256 thr / 8 warps = M128 x N128; grid 16x8x2 (z = K half) -> 256 CTAs.
// (R13-measured pipeline: early prefetch + wait_group 1.)
// ============================================================================
__global__ void __launch_bounds__(256, 2) k_fc1(int dummy) {
    extern __shared__ __align__(16) char smf[];
    const u32 sbase = (u32)__cvta_generic_to_shared(smf);

    const int tid = threadIdx.x;
    const int warp = tid >> 5, lane = tid & 31;
    const int wm = warp >> 1, wn = warp & 1;
    const int bm = blockIdx.x * 128, bn = blockIdx.y * 128;
    const int kz = blockIdx.z * 1568;

    const u32 lrow = (u32)((lane & 7) + ((lane >> 4) << 3));
    const u32 lkb16 = (u32)(((lane >> 3) & 1) << 4);
    const u32 arow16 = (u32)(lane & 15);
    const u32 acb16 = (u32)((lane >> 4) << 4);

    auto load_chunk = [&](int buf, int k0) {
        u32 abase = sbase + (u32)buf * 20480u;
        u32 bbase = sbase + 40960u + (u32)buf * 20480u;
        for (int i = tid; i < 2048; i += 256) {
            int sel = i >> 10;
            int r = i & 1023;
            int plane = r >> 9, rr = r & 511;
            int row = rr >> 2, qh = rr & 3;
            const u16* src;
            u32 dst;
            if (sel == 0) {
                src = (plane ? g_s2l : g_s2h) + (size_t)(bm + row) * 3136 + k0 + qh * 8;
                dst = abase;
            } else {
                src = (plane ? g_fc1wl : g_fc1wh) + (size_t)(bn + row) * 3136 + k0 + qh * 8;
                dst = bbase;
            }
            cp16u(dst + (u32)plane * 10240u + (u32)row * 80u + (u32)qh * 16u, src);
        }
    };

    load_chunk(0, kz);
    cp_commit();

    float d[2][8][4];
#pragma unroll
    for (int mt = 0; mt < 2; mt++)
#pragma unroll
        for (int nt = 0; nt < 8; nt++)
#pragma unroll
            for (int e = 0; e < 4; e++) d[mt][nt][e] = 0.f;

    for (int kt = 0; kt < 49; kt++) {
        if (kt < 48) {
            load_chunk((kt + 1) & 1, kz + (kt + 1) * 32);
            cp_commit();
            cp_wait1();
        } else {
            cp_wait0();
        }
        __syncthreads();

        const u32 abuf = sbase + (u32)(kt & 1) * 20480u;
        const u32 bbuf = sbase + 40960u + (u32)(kt & 1) * 20480u;

#pragma unroll
        for (int ks = 0; ks < 2; ks++) {
            u32 ah[2][4], al[2][4];
#pragma unroll
            for (int mt = 0; mt < 2; mt++) {
                u32 ar = abuf + ((u32)(wm * 32 + mt * 16) + arow16) * 80u
                       + (u32)ks * 32u + acb16;
                ldsm4(ah[mt][0], ah[mt][1], ah[mt][2], ah[mt][3], ar);
                ldsm4(al[mt][0], al[mt][1], al[mt][2], al[mt][3], ar + 10240u);
            }
            u32 bh[8][2], bl[8][2];
#pragma unroll
            for (int p = 0; p < 4; p++) {
                u32 ad = bbuf + ((u32)(wn * 64 + p * 16) + lrow) * 80u
                       + (u32)ks * 32u + lkb16;
                ldsm4(bh[2 * p][0], bh[2 * p][1], bh[2 * p + 1][0], bh[2 * p + 1][1], ad);
                ldsm4(bl[2 * p][0], bl[2 * p][1], bl[2 * p + 1][0], bl[2 * p + 1][1],
                      ad + 10240u);
            }
#pragma unroll
            for (int mt = 0; mt < 2; mt++)
#pragma unroll
                for (int nt = 0; nt < 8; nt++) mma16816(d[mt][nt], ah[mt], bh[nt]);
#pragma unroll
            for (int mt = 0; mt < 2; mt++)
#pragma unroll
                for (int nt = 0; nt < 8; nt++) mma16816(d[mt][nt], al[mt], bh[nt]);
#pragma unroll
            for (int mt = 0; mt < 2; mt++)
#pragma unroll
                for (int nt = 0; nt < 8; nt++) mma16816(d[mt][nt], ah[mt], bl[nt]);
        }
        __syncthreads();
    }

    float* outp = g_fc1p + (size_t)blockIdx.z * (2048 * 1024);
#pragma unroll
    for (int nt = 0; nt < 8; nt++) {
        int col = bn + wn * 64 + nt * 8 + (lane & 3) * 2;
#pragma unroll
        for (int mt = 0; mt < 2; mt++)
#pragma unroll
            for (int rp = 0; rp < 2; rp++) {
                int row = bm + wm * 32 + mt * 16 + (lane >> 2) + rp * 8;
                float2 o;
                o.x = d[mt][nt][2 * rp];
                o.y = d[mt][nt][2 * rp + 1];
                *reinterpret_cast<float2*>(&outp[(size_t)row * 1024 + col]) = o;
            }
    }
}

// ============================================================================
// fc2 fused: a = relu(p0 + p1 + b1), out = a @ fc2_w^T + b2. Warp per row.
// ============================================================================
__global__ void __launch_bounds__(256) k_fc2(const float* __restrict__ w,
                                             const float* __restrict__ b1,
                                             const float* __restrict__ b2,
                                             float* __restrict__ out) {
    __shared__ float sb1[1024];
    for (int i = threadIdx.x; i < 1024; i += 256) sb1[i] = b1[i];
    __syncthreads();

    int warp = threadIdx.x >> 5, lane = threadIdx.x & 31;
    int row = blockIdx.x * 8 + warp;
    const float* p0 = g_fc1p + (size_t)row * 1024;
    const float* p1 = g_fc1p + 2048 * 1024 + (size_t)row * 1024;
    float acc[10];
#pragma unroll
    for (int n = 0; n < 10; n++) acc[n] = 0.f;
    for (int k = lane; k < 1024; k += 32) {
        float av = fmaxf(p0[k] + p1[k] + sb1[k], 0.f);
#pragma unroll
        for (int n = 0; n < 10; n++) acc[n] += av * w[n * 1024 + k];
    }
#pragma unroll
    for (int n = 0; n < 10; n++)
#pragma unroll
        for (int off = 16; off > 0; off >>= 1)
            acc[n] += __shfl_xor_sync(0xffffffffu, acc[n], off);
    if (lane == 0) {
#pragma unroll
        for (int n = 0; n < 10; n++) out[row * 10 + n] = acc[n] + b2[n];
    }
}

// ============================================================================
extern "C" void kernel_launch(void* const* d_in, const int* in_sizes, int n_in,
                              void* d_out, int out_size) {
    const float* x       = (const float*)d_in[0];
    const float* conv1_w = (const float*)d_in[1];
    const float* trelu_t = (const float*)d_in[2];
    const float* conv2_w = (const float*)d_in[3];
    const float* conv2_b = (const float*)d_in[4];
    const float* fc1_w   = (const float*)d_in[5];
    const float* fc1_b   = (const float*)d_in[6];
    const float* fc2_w   = (const float*)d_in[7];
    const float* fc2_b   = (const float*)d_in[8];
    float* out = (float*)d_out;

    const int SMEM2 = 2 * 43008;
    const int SMEMF = 2 * 40960;
    cudaFuncSetAttribute(k_conv2, cudaFuncAttributeMaxDynamicSharedMemorySize, SMEM2);
    cudaFuncSetAttribute(k_fc1, cudaFuncAttributeMaxDynamicSharedMemorySize, SMEMF);

    // conv1 + both preps in one kernel (prep blocks overlap conv1's wave)
    k_conv1<<<2048 + 1024 + 138, 784>>>(x, conv1_w, trelu_t, conv2_w, fc1_w);
    k_conv2<<<1568, 256, SMEM2>>>(conv2_b);
    k_fc1<<<dim3(16, 8, 2), 256, SMEMF>>>(0);
    k_fc2<<<256, 256>>>(fc2_w, fc1_b, fc2_b, out);
}

// round 16
// speedup vs baseline: 1.0245x; 1.0140x over previous
#include <cuda_runtime.h>
#include <cuda_bf16.h>
#include <cstdint>

typedef unsigned long long ull;
typedef unsigned short u16;
typedef unsigned int u32;

// ---------------- device scratch (static, zero-initialized) ----------------
__device__ __align__(16) u16   g_s1p[2048 * 18 * 18 * 2 * 32]; // conv1 out packed, halo 0
__device__ __align__(16) u16   g_s2h[2048 * 3136];          // conv2 out bf16 hi [b][q*64+co]
__device__ __align__(16) u16   g_s2l[2048 * 3136];          // conv2 out bf16 lo
__device__ __align__(16) float g_fc1p[2 * 2048 * 1024];     // fc1 split-K partials
__device__ __align__(16) u16   g_fc1wh[1024 * 3136];        // fc1 w bf16 hi, K (q,co)
__device__ __align__(16) u16   g_fc1wl[1024 * 3136];        // fc1 w bf16 lo
__device__ __align__(16) u16   g_w2b[5 * 2 * 64 * 168];     // conv2 B [dy][plane][n][k pad 168]

// ---------------- f32x2 helpers ----------------
__device__ __forceinline__ ull ffma2(ull a, ull b, ull c) {
    ull d; asm("fma.rn.f32x2 %0, %1, %2, %3;" : "=l"(d) : "l"(a), "l"(b), "l"(c)); return d;
}
__device__ __forceinline__ ull dup2(float v) {
    ull d; asm("mov.b64 %0, {%1, %1};" : "=l"(d) : "f"(v)); return d;
}
__device__ __forceinline__ ull pk2(float lo, float hi) {
    ull d; asm("mov.b64 %0, {%1, %2};" : "=l"(d) : "f"(lo), "f"(hi)); return d;
}
__device__ __forceinline__ void upk2(ull v, float& lo, float& hi) {
    asm("mov.b64 {%0, %1}, %2;" : "=f"(lo), "=f"(hi) : "l"(v));
}

// ---------------- cp.async (.ca — the empirically faster config) ----------------
__device__ __forceinline__ void cp16u(u32 saddr, const void* g) {
    asm volatile("cp.async.ca.shared.global [%0], [%1], 16;" :: "r"(saddr), "l"(g));
}
__device__ __forceinline__ void cp_commit() { asm volatile("cp.async.commit_group;"); }
__device__ __forceinline__ void cp_wait0()  { asm volatile("cp.async.wait_group 0;"); }
__device__ __forceinline__ void cp_wait1()  { asm volatile("cp.async.wait_group 1;"); }

// ---------------- mma.sync / ldmatrix ----------------
__device__ __forceinline__ void ldsm4(u32& r0, u32& r1, u32& r2, u32& r3, u32 addr) {
    asm volatile("ldmatrix.sync.aligned.m8n8.x4.shared.b16 {%0,%1,%2,%3}, [%4];"
                 : "=r"(r0), "=r"(r1), "=r"(r2), "=r"(r3) : "r"(addr));
}
__device__ __forceinline__ void mma16816(float* d, const u32* a, const u32* b) {
    asm volatile("mma.sync.aligned.m16n8k16.row.col.f32.bf16.bf16.f32 "
                 "{%0,%1,%2,%3}, {%4,%5,%6,%7}, {%8,%9}, {%0,%1,%2,%3};"
                 : "+f"(d[0]), "+f"(d[1]), "+f"(d[2]), "+f"(d[3])
                 : "r"(a[0]), "r"(a[1]), "r"(a[2]), "r"(a[3]), "r"(b[0]), "r"(b[1]));
}

__device__ __forceinline__ void ins4(float& a, float& b, float& c, float& d, float v) {
    if (v > d) {
        d = v;
        if (d > c) { float t = c; c = d; d = t;
            if (c > b) { t = b; b = c; c = t;
                if (b > a) { t = a; a = b; b = t; }
            }
        }
    }
}
__device__ __forceinline__ u32 bf16pack2(float x, float y) {
    __nv_bfloat16 hx = __float2bfloat16(x), hy = __float2bfloat16(y);
    return (u32)reinterpret_cast<u16&>(hx) | ((u32)reinterpret_cast<u16&>(hy) << 16);
}

// ============================================================================
// conv1 + prep, fused as block ranges of one kernel (overlap in one wave):
//  blocks [0,2048)        : conv1 (1->32, 5x5, pad2) + top-4 + trelu + pool
//  blocks [2048,3072)     : fc1 weight permute + bf16 hi/lo split
//  blocks [3072,3210)     : conv2 B image build
// ============================================================================
__global__ void __launch_bounds__(784) k_conv1(const float* __restrict__ xin,
                                               const float* __restrict__ w1,
                                               const float* __restrict__ tt,
                                               const float* __restrict__ w2,
                                               const float* __restrict__ wfc) {
    __shared__ float s_img[1024];
    __shared__ ull   s_wp[400];
    __shared__ float s_t[32];

    const int tid = threadIdx.x;
    const int bid = blockIdx.x;

    if (bid >= 2048) {
        if (bid < 3072) {
            int n = bid - 2048;
            for (int i = tid; i < 3136; i += 784) {
                int q = i >> 6, co = i & 63;
                float v = wfc[n * 3136 + co * 49 + q];
                __nv_bfloat16 h = __float2bfloat16(v);
                __nv_bfloat16 l2 = __float2bfloat16(v - __bfloat162float(h));
                g_fc1wh[n * 3136 + i] = reinterpret_cast<u16&>(h);
                g_fc1wl[n * 3136 + i] = reinterpret_cast<u16&>(l2);
            }
        } else {
            int i = (bid - 3072) * 784 + tid;
            if (i < 5 * 2 * 64 * 168) {
                int dy = i / 21504, r = i % 21504;
                int plane = r / 10752, r2 = r % 10752;
                int co = r2 / 168, k = r2 % 168;
                float v = 0.f;
                if (k < 160) {
                    int dx = k >> 5, ci = k & 31;
                    v = w2[(co * 32 + ci) * 25 + dy * 5 + dx];
                }
                __nv_bfloat16 h = __float2bfloat16(v);
                if (plane == 0) {
                    g_w2b[i] = reinterpret_cast<u16&>(h);
                } else {
                    __nv_bfloat16 l2 = __float2bfloat16(v - __bfloat162float(h));
                    g_w2b[i] = reinterpret_cast<u16&>(l2);
                }
            }
        }
        return;
    }

    const int img = bid;

    for (int i = tid; i < 1024; i += 784) s_img[i] = 0.f;
    for (int i = tid; i < 400; i += 784) {
        int tap = i >> 4, c16 = i & 15;
        s_wp[i] = pk2(w1[(2 * c16) * 25 + tap], w1[(2 * c16 + 1) * 25 + tap]);
    }
    if (tid < 32) s_t[tid] = tt[tid];
    __syncthreads();
    {
        int y = tid / 28, xx = tid % 28;
        s_img[(y + 2) * 32 + xx + 2] = xin[img * 784 + tid];
    }
    __syncthreads();

    const int q = tid >> 2, j = tid & 3;
    const int PY = q / 14, PX = q % 14;
    const int py = 2 * PY + (j >> 1), px = 2 * PX + (j & 1);
    const float* base = &s_img[py * 32 + px];

    ull acc[16];
#pragma unroll
    for (int c = 0; c < 16; c++) acc[c] = 0ull;
#pragma unroll
    for (int dy = 0; dy < 5; dy++)
#pragma unroll
        for (int dx = 0; dx < 5; dx++) {
            ull wd = dup2(base[dy * 32 + dx]);
            const ull* wp = &s_wp[(dy * 5 + dx) * 16];
#pragma unroll
            for (int c = 0; c < 16; c++) acc[c] = ffma2(wd, wp[c], acc[c]);
        }

    float vals[32];
#pragma unroll
    for (int c = 0; c < 16; c++) upk2(acc[c], vals[2 * c], vals[2 * c + 1]);

    float a4 = -3.4e38f, b4 = -3.4e38f, c4 = -3.4e38f, d4 = -3.4e38f;
#pragma unroll
    for (int c = 0; c < 32; c++) ins4(a4, b4, c4, d4, vals[c]);

    const u32 lane = (u32)(tid & 31);
    const u32 qm = 0xFu << (lane & ~3u);
#pragma unroll
    for (int c = 0; c < 32; c++) {
        float v = vals[c];
        float r = (v >= d4) ? fmaxf(v - s_t[c], 0.f) : 0.f;
        r = fmaxf(r, __shfl_xor_sync(qm, r, 1));
        r = fmaxf(r, __shfl_xor_sync(qm, r, 2));
        vals[c] = r;
    }

    if (j == 0) {
        u16 oh[32], ol[32];
#pragma unroll
        for (int c = 0; c < 32; c++) {
            float v = vals[c];
            __nv_bfloat16 h = __float2bfloat16(v);
            oh[c] = reinterpret_cast<u16&>(h);
            __nv_bfloat16 l2 = __float2bfloat16(v - __bfloat162float(h));
            ol[c] = reinterpret_cast<u16&>(l2);
        }
        size_t gb = ((((size_t)img * 18 + (PY + 2)) * 18 + (PX + 2)) * 2) * 32;
#pragma unroll
        for (int g = 0; g < 2; g++) {
#pragma unroll
            for (int c = 0; c < 4; c++) {
                __align__(16) u16 buf[8];
                buf[0] = oh[g * 16 + 2 * c];     buf[1] = oh[g * 16 + 2 * c + 1];
                buf[2] = ol[g * 16 + 2 * c];     buf[3] = ol[g * 16 + 2 * c + 1];
                buf[4] = oh[g * 16 + 2 * c + 8]; buf[5] = oh[g * 16 + 2 * c + 9];
                buf[6] = ol[g * 16 + 2 * c + 8]; buf[7] = ol[g * 16 + 2 * c + 9];
                *reinterpret_cast<uint4*>(g_s1p + gb + g * 32 + c * 8) =
                    *reinterpret_cast<uint4*>(buf);
            }
        }
    }
}

// ============================================================================
// conv2 via mma.sync (bf16 hi/lo x3): 5 accumulated GEMMs, K=160 per dy.
// CTA = 256 threads / 8 warps, M=256 rows; warp = m32 x n64, 2 CTAs/SM.
// ============================================================================
__global__ void __launch_bounds__(256, 2) k_conv2(const float* __restrict__ b2) {
    extern __shared__ __align__(16) char sm2[];
    u32 sB = (u32)__cvta_generic_to_shared(sm2);   // 2 x 43008 B buffers

    const int tid = threadIdx.x;
    const int warp = tid >> 5, lane = tid & 31;

    u32 grpb[4];
#pragma unroll
    for (int i = 0; i < 4; i++) {
        int r = warp * 32 + ((i & 1) << 3) + ((i >> 1) << 4) + (lane >> 2);
        int m = blockIdx.x * 256 + r;
        int g = m >> 2, j = m & 3;
        int b = g / 49, q = g % 49;
        int qy = q / 7, qx = q % 7;
        int py = 2 * qy + (j >> 1), px = 2 * qx + (j & 1);
        grpb[i] = (u32)(((b * 18 + py) * 18 + px) * 2) * 32u + (u32)(lane & 3) * 8u;
    }
    const u16* __restrict__ pp = g_s1p;

    for (int i = tid; i < 2688; i += 256)
        cp16u(sB + (u32)i * 16u, (const char*)g_w2b + (size_t)i * 16);
    cp_commit();

    float d[2][8][4];
#pragma unroll
    for (int mt = 0; mt < 2; mt++)
#pragma unroll
        for (int nt = 0; nt < 8; nt++)
#pragma unroll
            for (int e = 0; e < 4; e++) d[mt][nt][e] = 0.f;

    const u32 lrow = (u32)((lane & 7) + ((lane >> 4) << 3));
    const u32 lkb16 = (u32)(((lane >> 3) & 1) << 4);

    for (int dy = 0; dy < 5; dy++) {
        if (dy < 4) {
            u32 dst = sB + (u32)((dy + 1) & 1) * 43008u;
            const char* src = (const char*)g_w2b + (size_t)(dy + 1) * 43008u;
            for (int i = tid; i < 2688; i += 256)
                cp16u(dst + (u32)i * 16u, src + (size_t)i * 16);
            cp_commit();
            cp_wait1();
        } else {
            cp_wait0();
        }
        __syncthreads();

        const u32 dygrp = (u32)dy * 36u;
        const u32 bb = sB + (u32)(dy & 1) * 43008u;

#pragma unroll
        for (int s = 0; s < 10; s++) {
            const u32 goff = (dygrp + (u32)s) * 32u;
            u32 ah[2][4], al[2][4];
#pragma unroll
            for (int mt = 0; mt < 2; mt++) {
                uint4 q0 = *reinterpret_cast<const uint4*>(pp + grpb[mt * 2] + goff);
                uint4 q1 = *reinterpret_cast<const uint4*>(pp + grpb[mt * 2 + 1] + goff);
                ah[mt][0] = q0.x; al[mt][0] = q0.y; ah[mt][2] = q0.z; al[mt][2] = q0.w;
                ah[mt][1] = q1.x; al[mt][1] = q1.y; ah[mt][3] = q1.z; al[mt][3] = q1.w;
            }
            u32 bh[8][2], bl[8][2];
#pragma unroll
            for (int p = 0; p < 4; p++) {
                u32 ad = bb + ((u32)p * 16u + lrow) * 336u + (u32)s * 32u + lkb16;
                ldsm4(bh[2 * p][0], bh[2 * p][1], bh[2 * p + 1][0], bh[2 * p + 1][1], ad);
                ldsm4(bl[2 * p][0], bl[2 * p][1], bl[2 * p + 1][0], bl[2 * p + 1][1],
                      ad + 21504u);
            }
#pragma unroll
            for (int mt = 0; mt < 2; mt++)
#pragma unroll
                for (int nt = 0; nt < 8; nt++) mma16816(d[mt][nt], ah[mt], bh[nt]);
#pragma unroll
            for (int mt = 0; mt < 2; mt++)
#pragma unroll
                for (int nt = 0; nt < 8; nt++) mma16816(d[mt][nt], al[mt], bh[nt]);
#pragma unroll
            for (int mt = 0; mt < 2; mt++)
#pragma unroll
                for (int nt = 0; nt < 8; nt++) mma16816(d[mt][nt], ah[mt], bl[nt]);
        }
        __syncthreads();
    }

    // epilogue: quad max-pool + bias + relu -> bf16 hi/lo planes
    float bA[8], bB[8];
#pragma unroll
    for (int nt = 0; nt < 8; nt++) {
        int co = nt * 8 + 2 * (lane & 3);
        bA[nt] = b2[co]; bB[nt] = b2[co + 1];
    }
    bool act = ((lane & 12) == 0);
#pragma unroll
    for (int mt = 0; mt < 2; mt++)
#pragma unroll
        for (int rp = 0; rp < 2; rp++) {
            int G = blockIdx.x * 64 + warp * 8 + mt * 4 + rp * 2 + (lane >> 4);
            int b_ = G / 49, q_ = G % 49;
            size_t obase = (size_t)b_ * 3136 + q_ * 64;
#pragma unroll
            for (int nt = 0; nt < 8; nt++) {
                float v0 = d[mt][nt][2 * rp];
                float v1 = d[mt][nt][2 * rp + 1];
                v0 = fmaxf(v0, __shfl_xor_sync(0xffffffffu, v0, 4));
                v0 = fmaxf(v0, __shfl_xor_sync(0xffffffffu, v0, 8));
                v1 = fmaxf(v1, __shfl_xor_sync(0xffffffffu, v1, 4));
                v1 = fmaxf(v1, __shfl_xor_sync(0xffffffffu, v1, 8));
                if (act) {
                    float ox = fmaxf(v0 + bA[nt], 0.f);
                    float oy = fmaxf(v1 + bB[nt], 0.f);
                    __nv_bfloat16 hx = __float2bfloat16(ox), hy = __float2bfloat16(oy);
                    float lx = ox - __bfloat162float(hx);
                    float ly = oy - __bfloat162float(hy);
                    size_t idx = obase + nt * 8 + 2 * (lane & 3);
                    *reinterpret_cast<u32*>(g_s2h + idx) =
                        (u32)reinterpret_cast<u16&>(hx) | ((u32)reinterpret_cast<u16&>(hy) << 16);
                    *reinterpret_cast<u32*>(g_s2l + idx) = bf16pack2(lx, ly);
                }
            }
        }
}

// ============================================================================
// fc1 split-K via mma.sync (bf16 hi/lo x3): M=2048, N=1024, K=3136.
// CTA 256 thr / 8 warps = M128 x N128; grid 16x8x2 (z = K half) -> 256 CTAs.
// ============================================================================
__global__ void __launch_bounds__(256, 2) k_fc1(int dummy) {
    extern __shared__ __align__(16) char smf[];
    const u32 sbase = (u32)__cvta_generic_to_shared(smf);

    const int tid = threadIdx.x;
    const int warp = tid >> 5, lane = tid & 31;
    const int wm = warp >> 1, wn = warp & 1;
    const int bm = blockIdx.x * 128, bn = blockIdx.y * 128;
    const int kz = blockIdx.z * 1568;

    const u32 lrow = (u32)((lane & 7) + ((lane >> 4) << 3));
    const u32 lkb16 = (u32)(((lane >> 3) & 1) << 4);
    const u32 arow16 = (u32)(lane & 15);
    const u32 acb16 = (u32)((lane >> 4) << 4);

    auto load_chunk = [&](int buf, int k0) {
        u32 abase = sbase + (u32)buf * 20480u;
        u32 bbase = sbase + 40960u + (u32)buf * 20480u;
        for (int i = tid; i < 2048; i += 256) {
            int sel = i >> 10;
            int r = i & 1023;
            int plane = r >> 9, rr = r & 511;
            int row = rr >> 2, qh = rr & 3;
            const u16* src;
            u32 dst;
            if (sel == 0) {
                src = (plane ? g_s2l : g_s2h) + (size_t)(bm + row) * 3136 + k0 + qh * 8;
                dst = abase;
            } else {
                src = (plane ? g_fc1wl : g_fc1wh) + (size_t)(bn + row) * 3136 + k0 + qh * 8;
                dst = bbase;
            }
            cp16u(dst + (u32)plane * 10240u + (u32)row * 80u + (u32)qh * 16u, src);
        }
    };

    load_chunk(0, kz);
    cp_commit();

    float d[2][8][4];
#pragma unroll
    for (int mt = 0; mt < 2; mt++)
#pragma unroll
        for (int nt = 0; nt < 8; nt++)
#pragma unroll
            for (int e = 0; e < 4; e++) d[mt][nt][e] = 0.f;

    for (int kt = 0; kt < 49; kt++) {
        if (kt < 48) {
            load_chunk((kt + 1) & 1, kz + (kt + 1) * 32);
            cp_commit();
            cp_wait1();
        } else {
            cp_wait0();
        }
        __syncthreads();

        const u32 abuf = sbase + (u32)(kt & 1) * 20480u;
        const u32 bbuf = sbase + 40960u + (u32)(kt & 1) * 20480u;

#pragma unroll
        for (int ks = 0; ks < 2; ks++) {
            u32 ah[2][4], al[2][4];
#pragma unroll
            for (int mt = 0; mt < 2; mt++) {
                u32 ar = abuf + ((u32)(wm * 32 + mt * 16) + arow16) * 80u
                       + (u32)ks * 32u + acb16;
                ldsm4(ah[mt][0], ah[mt][1], ah[mt][2], ah[mt][3], ar);
                ldsm4(al[mt][0], al[mt][1], al[mt][2], al[mt][3], ar + 10240u);
            }
            u32 bh[8][2], bl[8][2];
#pragma unroll
            for (int p = 0; p < 4; p++) {
                u32 ad = bbuf + ((u32)(wn * 64 + p * 16) + lrow) * 80u
                       + (u32)ks * 32u + lkb16;
                ldsm4(bh[2 * p][0], bh[2 * p][1], bh[2 * p + 1][0], bh[2 * p + 1][1], ad);
                ldsm4(bl[2 * p][0], bl[2 * p][1], bl[2 * p + 1][0], bl[2 * p + 1][1],
                      ad + 10240u);
            }
#pragma unroll
            for (int mt = 0; mt < 2; mt++)
#pragma unroll
                for (int nt = 0; nt < 8; nt++) mma16816(d[mt][nt], ah[mt], bh[nt]);
#pragma unroll
            for (int mt = 0; mt < 2; mt++)
#pragma unroll
                for (int nt = 0; nt < 8; nt++) mma16816(d[mt][nt], al[mt], bh[nt]);
#pragma unroll
            for (int mt = 0; mt < 2; mt++)
#pragma unroll
                for (int nt = 0; nt < 8; nt++) mma16816(d[mt][nt], ah[mt], bl[nt]);
        }
        __syncthreads();
    }

    float* outp = g_fc1p + (size_t)blockIdx.z * (2048 * 1024);
#pragma unroll
    for (int nt = 0; nt < 8; nt++) {
        int col = bn + wn * 64 + nt * 8 + (lane & 3) * 2;
#pragma unroll
        for (int mt = 0; mt < 2; mt++)
#pragma unroll
            for (int rp = 0; rp < 2; rp++) {
                int row = bm + wm * 32 + mt * 16 + (lane >> 2) + rp * 8;
                float2 o;
                o.x = d[mt][nt][2 * rp];
                o.y = d[mt][nt][2 * rp + 1];
                *reinterpret_cast<float2*>(&outp[(size_t)row * 1024 + col]) = o;
            }
    }
}

// ============================================================================
// fc2 fused, vectorized: a = relu(p0 + p1 + b1), out = a @ fc2_w^T + b2.
// Warp per row; lane owns float4 chunks (8 iters), w L1-hot.
// ============================================================================
__global__ void __launch_bounds__(256) k_fc2(const float* __restrict__ w,
                                             const float* __restrict__ b1,
                                             const float* __restrict__ b2,
                                             float* __restrict__ out) {
    __shared__ float sb1[1024];
    for (int i = threadIdx.x; i < 1024; i += 256) sb1[i] = b1[i];
    __syncthreads();

    int warp = threadIdx.x >> 5, lane = threadIdx.x & 31;
    int row = blockIdx.x * 8 + warp;
    const float4* p0 = reinterpret_cast<const float4*>(g_fc1p + (size_t)row * 1024);
    const float4* p1 = reinterpret_cast<const float4*>(g_fc1p + 2048 * 1024 + (size_t)row * 1024);

    float acc[10];
#pragma unroll
    for (int n = 0; n < 10; n++) acc[n] = 0.f;

#pragma unroll
    for (int it = 0; it < 8; it++) {
        int k4 = it * 32 + lane;                   // float4 index within row
        float4 a0 = p0[k4];
        float4 a1 = p1[k4];
        float4 bb = *reinterpret_cast<const float4*>(sb1 + k4 * 4);
        float4 av;
        av.x = fmaxf(a0.x + a1.x + bb.x, 0.f);
        av.y = fmaxf(a0.y + a1.y + bb.y, 0.f);
        av.z = fmaxf(a0.z + a1.z + bb.z, 0.f);
        av.w = fmaxf(a0.w + a1.w + bb.w, 0.f);
#pragma unroll
        for (int n = 0; n < 10; n++) {
            float4 wv = *reinterpret_cast<const float4*>(w + n * 1024 + k4 * 4);
            acc[n] += av.x * wv.x + av.y * wv.y + av.z * wv.z + av.w * wv.w;
        }
    }
#pragma unroll
    for (int n = 0; n < 10; n++)
#pragma unroll
        for (int off = 16; off > 0; off >>= 1)
            acc[n] += __shfl_xor_sync(0xffffffffu, acc[n], off);
    if (lane == 0) {
#pragma unroll
        for (int n = 0; n < 10; n++) out[row * 10 + n] = acc[n] + b2[n];
    }
}

// ============================================================================
extern "C" void kernel_launch(void* const* d_in, const int* in_sizes, int n_in,
                              void* d_out, int out_size) {
    const float* x       = (const float*)d_in[0];
    const float* conv1_w = (const float*)d_in[1];
    const float* trelu_t = (const float*)d_in[2];
    const float* conv2_w = (const float*)d_in[3];
    const float* conv2_b = (const float*)d_in[4];
    const float* fc1_w   = (const float*)d_in[5];
    const float* fc1_b   = (const float*)d_in[6];
    const float* fc2_w   = (const float*)d_in[7];
    const float* fc2_b   = (const float*)d_in[8];
    float* out = (float*)d_out;

    const int SMEM2 = 2 * 43008;
    const int SMEMF = 2 * 40960;
    cudaFuncSetAttribute(k_conv2, cudaFuncAttributeMaxDynamicSharedMemorySize, SMEM2);
    cudaFuncSetAttribute(k_fc1, cudaFuncAttributeMaxDynamicSharedMemorySize, SMEMF);

    k_conv1<<<2048 + 1024 + 138, 784>>>(x, conv1_w, trelu_t, conv2_w, fc1_w);
    k_conv2<<<1568, 256, SMEM2>>>(conv2_b);
    k_fc1<<<dim3(16, 8, 2), 256, SMEMF>>>(0);
    k_fc2<<<256, 256>>>(fc2_w, fc1_b, fc2_b, out);
}

// round 17
// speedup vs baseline: 1.0335x; 1.0087x over previous
#include <cuda_runtime.h>
#include <cuda_bf16.h>
#include <cstdint>

typedef unsigned long long ull;
typedef unsigned short u16;
typedef unsigned int u32;

// ---------------- device scratch (static, zero-initialized) ----------------
__device__ __align__(16) u16   g_s1p[2048 * 18 * 18 * 2 * 32]; // conv1 out packed, halo 0
__device__ __align__(16) u16   g_s2h[2048 * 3136];          // conv2 out bf16 hi [b][q*64+co]
__device__ __align__(16) u16   g_s2l[2048 * 3136];          // conv2 out bf16 lo
__device__ __align__(16) float g_fc1p[2 * 2048 * 1024];     // fc1 split-K partials
__device__ __align__(16) u16   g_fc1wh[1024 * 3136];        // fc1 w bf16 hi, K (q,co)
__device__ __align__(16) u16   g_fc1wl[1024 * 3136];        // fc1 w bf16 lo
__device__ __align__(16) u16   g_w2b[5 * 2 * 64 * 168];     // conv2 B [dy][plane][n][k pad 168]

// ---------------- f32x2 helpers ----------------
__device__ __forceinline__ ull ffma2(ull a, ull b, ull c) {
    ull d; asm("fma.rn.f32x2 %0, %1, %2, %3;" : "=l"(d) : "l"(a), "l"(b), "l"(c)); return d;
}
__device__ __forceinline__ ull dup2(float v) {
    ull d; asm("mov.b64 %0, {%1, %1};" : "=l"(d) : "f"(v)); return d;
}
__device__ __forceinline__ ull pk2(float lo, float hi) {
    ull d; asm("mov.b64 %0, {%1, %2};" : "=l"(d) : "f"(lo), "f"(hi)); return d;
}
__device__ __forceinline__ void upk2(ull v, float& lo, float& hi) {
    asm("mov.b64 {%0, %1}, %2;" : "=f"(lo), "=f"(hi) : "l"(v));
}

// ---------------- cp.async (.ca — the empirically faster config) ----------------
__device__ __forceinline__ void cp16u(u32 saddr, const void* g) {
    asm volatile("cp.async.ca.shared.global [%0], [%1], 16;" :: "r"(saddr), "l"(g));
}
__device__ __forceinline__ void cp_commit() { asm volatile("cp.async.commit_group;"); }
__device__ __forceinline__ void cp_wait0()  { asm volatile("cp.async.wait_group 0;"); }
__device__ __forceinline__ void cp_wait1()  { asm volatile("cp.async.wait_group 1;"); }

// ---------------- mma.sync / ldmatrix ----------------
__device__ __forceinline__ void ldsm4(u32& r0, u32& r1, u32& r2, u32& r3, u32 addr) {
    asm volatile("ldmatrix.sync.aligned.m8n8.x4.shared.b16 {%0,%1,%2,%3}, [%4];"
                 : "=r"(r0), "=r"(r1), "=r"(r2), "=r"(r3) : "r"(addr));
}
__device__ __forceinline__ void mma16816(float* d, const u32* a, const u32* b) {
    asm volatile("mma.sync.aligned.m16n8k16.row.col.f32.bf16.bf16.f32 "
                 "{%0,%1,%2,%3}, {%4,%5,%6,%7}, {%8,%9}, {%0,%1,%2,%3};"
                 : "+f"(d[0]), "+f"(d[1]), "+f"(d[2]), "+f"(d[3])
                 : "r"(a[0]), "r"(a[1]), "r"(a[2]), "r"(a[3]), "r"(b[0]), "r"(b[1]));
}

__device__ __forceinline__ void ins4(float& a, float& b, float& c, float& d, float v) {
    if (v > d) {
        d = v;
        if (d > c) { float t = c; c = d; d = t;
            if (c > b) { t = b; b = c; c = t;
                if (b > a) { t = a; a = b; b = t; }
            }
        }
    }
}
__device__ __forceinline__ u32 bf16pack2(float x, float y) {
    __nv_bfloat16 hx = __float2bfloat16(x), hy = __float2bfloat16(y);
    return (u32)reinterpret_cast<u16&>(hx) | ((u32)reinterpret_cast<u16&>(hy) << 16);
}

// ============================================================================
// conv1 + prep, fused as block ranges of one kernel (overlap in one wave):
//  blocks [0,2048)        : conv1 (1->32, 5x5, pad2) + top-4 + trelu + pool
//  blocks [2048,3072)     : fc1 weight permute + bf16 hi/lo split
//  blocks [3072,3210)     : conv2 B image build
// ============================================================================
__global__ void __launch_bounds__(784) k_conv1(const float* __restrict__ xin,
                                               const float* __restrict__ w1,
                                               const float* __restrict__ tt,
                                               const float* __restrict__ w2,
                                               const float* __restrict__ wfc) {
    __shared__ float s_img[1024];
    __shared__ ull   s_wp[400];
    __shared__ float s_t[32];

    const int tid = threadIdx.x;
    const int bid = blockIdx.x;

    if (bid >= 2048) {
        if (bid < 3072) {
            int n = bid - 2048;
            for (int i = tid; i < 3136; i += 784) {
                int q = i >> 6, co = i & 63;
                float v = wfc[n * 3136 + co * 49 + q];
                __nv_bfloat16 h = __float2bfloat16(v);
                __nv_bfloat16 l2 = __float2bfloat16(v - __bfloat162float(h));
                g_fc1wh[n * 3136 + i] = reinterpret_cast<u16&>(h);
                g_fc1wl[n * 3136 + i] = reinterpret_cast<u16&>(l2);
            }
        } else {
            int i = (bid - 3072) * 784 + tid;
            if (i < 5 * 2 * 64 * 168) {
                int dy = i / 21504, r = i % 21504;
                int plane = r / 10752, r2 = r % 10752;
                int co = r2 / 168, k = r2 % 168;
                float v = 0.f;
                if (k < 160) {
                    int dx = k >> 5, ci = k & 31;
                    v = w2[(co * 32 + ci) * 25 + dy * 5 + dx];
                }
                __nv_bfloat16 h = __float2bfloat16(v);
                if (plane == 0) {
                    g_w2b[i] = reinterpret_cast<u16&>(h);
                } else {
                    __nv_bfloat16 l2 = __float2bfloat16(v - __bfloat162float(h));
                    g_w2b[i] = reinterpret_cast<u16&>(l2);
                }
            }
        }
        return;
    }

    const int img = bid;

    for (int i = tid; i < 1024; i += 784) s_img[i] = 0.f;
    for (int i = tid; i < 400; i += 784) {
        int tap = i >> 4, c16 = i & 15;
        s_wp[i] = pk2(w1[(2 * c16) * 25 + tap], w1[(2 * c16 + 1) * 25 + tap]);
    }
    if (tid < 32) s_t[tid] = tt[tid];
    __syncthreads();
    {
        int y = tid / 28, xx = tid % 28;
        s_img[(y + 2) * 32 + xx + 2] = xin[img * 784 + tid];
    }
    __syncthreads();

    const int q = tid >> 2, j = tid & 3;
    const int PY = q / 14, PX = q % 14;
    const int py = 2 * PY + (j >> 1), px = 2 * PX + (j & 1);
    const float* base = &s_img[py * 32 + px];

    ull acc[16];
#pragma unroll
    for (int c = 0; c < 16; c++) acc[c] = 0ull;
#pragma unroll
    for (int dy = 0; dy < 5; dy++)
#pragma unroll
        for (int dx = 0; dx < 5; dx++) {
            ull wd = dup2(base[dy * 32 + dx]);
            const ull* wp = &s_wp[(dy * 5 + dx) * 16];
#pragma unroll
            for (int c = 0; c < 16; c++) acc[c] = ffma2(wd, wp[c], acc[c]);
        }

    float vals[32];
#pragma unroll
    for (int c = 0; c < 16; c++) upk2(acc[c], vals[2 * c], vals[2 * c + 1]);

    float a4 = -3.4e38f, b4 = -3.4e38f, c4 = -3.4e38f, d4 = -3.4e38f;
#pragma unroll
    for (int c = 0; c < 32; c++) ins4(a4, b4, c4, d4, vals[c]);

    const u32 lane = (u32)(tid & 31);
    const u32 qm = 0xFu << (lane & ~3u);
#pragma unroll
    for (int c = 0; c < 32; c++) {
        float v = vals[c];
        float r = (v >= d4) ? fmaxf(v - s_t[c], 0.f) : 0.f;
        r = fmaxf(r, __shfl_xor_sync(qm, r, 1));
        r = fmaxf(r, __shfl_xor_sync(qm, r, 2));
        vals[c] = r;
    }

    if (j == 0) {
        u16 oh[32], ol[32];
#pragma unroll
        for (int c = 0; c < 32; c++) {
            float v = vals[c];
            __nv_bfloat16 h = __float2bfloat16(v);
            oh[c] = reinterpret_cast<u16&>(h);
            __nv_bfloat16 l2 = __float2bfloat16(v - __bfloat162float(h));
            ol[c] = reinterpret_cast<u16&>(l2);
        }
        size_t gb = ((((size_t)img * 18 + (PY + 2)) * 18 + (PX + 2)) * 2) * 32;
#pragma unroll
        for (int g = 0; g < 2; g++) {
#pragma unroll
            for (int c = 0; c < 4; c++) {
                __align__(16) u16 buf[8];
                buf[0] = oh[g * 16 + 2 * c];     buf[1] = oh[g * 16 + 2 * c + 1];
                buf[2] = ol[g * 16 + 2 * c];     buf[3] = ol[g * 16 + 2 * c + 1];
                buf[4] = oh[g * 16 + 2 * c + 8]; buf[5] = oh[g * 16 + 2 * c + 9];
                buf[6] = ol[g * 16 + 2 * c + 8]; buf[7] = ol[g * 16 + 2 * c + 9];
                *reinterpret_cast<uint4*>(g_s1p + gb + g * 32 + c * 8) =
                    *reinterpret_cast<uint4*>(buf);
            }
        }
    }
}

// ============================================================================
// conv2 via mma.sync (bf16 hi/lo x3): 5 accumulated GEMMs, K=160 per dy.
// CTA = 256 threads / 8 warps, M=256 rows; warp = m32 x n64, 2 CTAs/SM.
// ============================================================================
__global__ void __launch_bounds__(256, 2) k_conv2(const float* __restrict__ b2) {
    extern __shared__ __align__(16) char sm2[];
    u32 sB = (u32)__cvta_generic_to_shared(sm2);   // 2 x 43008 B buffers

    const int tid = threadIdx.x;
    const int warp = tid >> 5, lane = tid & 31;

    u32 grpb[4];
#pragma unroll
    for (int i = 0; i < 4; i++) {
        int r = warp * 32 + ((i & 1) << 3) + ((i >> 1) << 4) + (lane >> 2);
        int m = blockIdx.x * 256 + r;
        int g = m >> 2, j = m & 3;
        int b = g / 49, q = g % 49;
        int qy = q / 7, qx = q % 7;
        int py = 2 * qy + (j >> 1), px = 2 * qx + (j & 1);
        grpb[i] = (u32)(((b * 18 + py) * 18 + px) * 2) * 32u + (u32)(lane & 3) * 8u;
    }
    const u16* __restrict__ pp = g_s1p;

    for (int i = tid; i < 2688; i += 256)
        cp16u(sB + (u32)i * 16u, (const char*)g_w2b + (size_t)i * 16);
    cp_commit();

    float d[2][8][4];
#pragma unroll
    for (int mt = 0; mt < 2; mt++)
#pragma unroll
        for (int nt = 0; nt < 8; nt++)
#pragma unroll
            for (int e = 0; e < 4; e++) d[mt][nt][e] = 0.f;

    const u32 lrow = (u32)((lane & 7) + ((lane >> 4) << 3));
    const u32 lkb16 = (u32)(((lane >> 3) & 1) << 4);

    for (int dy = 0; dy < 5; dy++) {
        if (dy < 4) {
            u32 dst = sB + (u32)((dy + 1) & 1) * 43008u;
            const char* src = (const char*)g_w2b + (size_t)(dy + 1) * 43008u;
            for (int i = tid; i < 2688; i += 256)
                cp16u(dst + (u32)i * 16u, src + (size_t)i * 16);
            cp_commit();
            cp_wait1();
        } else {
            cp_wait0();
        }
        __syncthreads();

        const u32 dygrp = (u32)dy * 36u;
        const u32 bb = sB + (u32)(dy & 1) * 43008u;

#pragma unroll
        for (int s = 0; s < 10; s++) {
            const u32 goff = (dygrp + (u32)s) * 32u;
            u32 ah[2][4], al[2][4];
#pragma unroll
            for (int mt = 0; mt < 2; mt++) {
                uint4 q0 = *reinterpret_cast<const uint4*>(pp + grpb[mt * 2] + goff);
                uint4 q1 = *reinterpret_cast<const uint4*>(pp + grpb[mt * 2 + 1] + goff);
                ah[mt][0] = q0.x; al[mt][0] = q0.y; ah[mt][2] = q0.z; al[mt][2] = q0.w;
                ah[mt][1] = q1.x; al[mt][1] = q1.y; ah[mt][3] = q1.z; al[mt][3] = q1.w;
            }
            u32 bh[8][2], bl[8][2];
#pragma unroll
            for (int p = 0; p < 4; p++) {
                u32 ad = bb + ((u32)p * 16u + lrow) * 336u + (u32)s * 32u + lkb16;
                ldsm4(bh[2 * p][0], bh[2 * p][1], bh[2 * p + 1][0], bh[2 * p + 1][1], ad);
                ldsm4(bl[2 * p][0], bl[2 * p][1], bl[2 * p + 1][0], bl[2 * p + 1][1],
                      ad + 21504u);
            }
#pragma unroll
            for (int mt = 0; mt < 2; mt++)
#pragma unroll
                for (int nt = 0; nt < 8; nt++) mma16816(d[mt][nt], ah[mt], bh[nt]);
#pragma unroll
            for (int mt = 0; mt < 2; mt++)
#pragma unroll
                for (int nt = 0; nt < 8; nt++) mma16816(d[mt][nt], al[mt], bh[nt]);
#pragma unroll
            for (int mt = 0; mt < 2; mt++)
#pragma unroll
                for (int nt = 0; nt < 8; nt++) mma16816(d[mt][nt], ah[mt], bl[nt]);
        }
        __syncthreads();
    }

    // epilogue: quad max-pool + bias + relu -> bf16 hi/lo planes
    float bA[8], bB[8];
#pragma unroll
    for (int nt = 0; nt < 8; nt++) {
        int co = nt * 8 + 2 * (lane & 3);
        bA[nt] = b2[co]; bB[nt] = b2[co + 1];
    }
    bool act = ((lane & 12) == 0);
#pragma unroll
    for (int mt = 0; mt < 2; mt++)
#pragma unroll
        for (int rp = 0; rp < 2; rp++) {
            int G = blockIdx.x * 64 + warp * 8 + mt * 4 + rp * 2 + (lane >> 4);
            int b_ = G / 49, q_ = G % 49;
            size_t obase = (size_t)b_ * 3136 + q_ * 64;
#pragma unroll
            for (int nt = 0; nt < 8; nt++) {
                float v0 = d[mt][nt][2 * rp];
                float v1 = d[mt][nt][2 * rp + 1];
                v0 = fmaxf(v0, __shfl_xor_sync(0xffffffffu, v0, 4));
                v0 = fmaxf(v0, __shfl_xor_sync(0xffffffffu, v0, 8));
                v1 = fmaxf(v1, __shfl_xor_sync(0xffffffffu, v1, 4));
                v1 = fmaxf(v1, __shfl_xor_sync(0xffffffffu, v1, 8));
                if (act) {
                    float ox = fmaxf(v0 + bA[nt], 0.f);
                    float oy = fmaxf(v1 + bB[nt], 0.f);
                    __nv_bfloat16 hx = __float2bfloat16(ox), hy = __float2bfloat16(oy);
                    float lx = ox - __bfloat162float(hx);
                    float ly = oy - __bfloat162float(hy);
                    size_t idx = obase + nt * 8 + 2 * (lane & 3);
                    *reinterpret_cast<u32*>(g_s2h + idx) =
                        (u32)reinterpret_cast<u16&>(hx) | ((u32)reinterpret_cast<u16&>(hy) << 16);
                    *reinterpret_cast<u32*>(g_s2l + idx) = bf16pack2(lx, ly);
                }
            }
        }
}

// ============================================================================
// fc1 split-K via mma.sync (bf16 hi/lo x3): M=2048, N=1024, K=3136.
// CTA 256 thr / 8 warps = M128 x N128; grid 16x8x2 (z = K half) -> 256 CTAs.
// ============================================================================
__global__ void __launch_bounds__(256, 2) k_fc1(int dummy) {
    extern __shared__ __align__(16) char smf[];
    const u32 sbase = (u32)__cvta_generic_to_shared(smf);

    const int tid = threadIdx.x;
    const int warp = tid >> 5, lane = tid & 31;
    const int wm = warp >> 1, wn = warp & 1;
    const int bm = blockIdx.x * 128, bn = blockIdx.y * 128;
    const int kz = blockIdx.z * 1568;

    const u32 lrow = (u32)((lane & 7) + ((lane >> 4) << 3));
    const u32 lkb16 = (u32)(((lane >> 3) & 1) << 4);
    const u32 arow16 = (u32)(lane & 15);
    const u32 acb16 = (u32)((lane >> 4) << 4);

    auto load_chunk = [&](int buf, int k0) {
        u32 abase = sbase + (u32)buf * 20480u;
        u32 bbase = sbase + 40960u + (u32)buf * 20480u;
        for (int i = tid; i < 2048; i += 256) {
            int sel = i >> 10;
            int r = i & 1023;
            int plane = r >> 9, rr = r & 511;
            int row = rr >> 2, qh = rr & 3;
            const u16* src;
            u32 dst;
            if (sel == 0) {
                src = (plane ? g_s2l : g_s2h) + (size_t)(bm + row) * 3136 + k0 + qh * 8;
                dst = abase;
            } else {
                src = (plane ? g_fc1wl : g_fc1wh) + (size_t)(bn + row) * 3136 + k0 + qh * 8;
                dst = bbase;
            }
            cp16u(dst + (u32)plane * 10240u + (u32)row * 80u + (u32)qh * 16u, src);
        }
    };

    load_chunk(0, kz);
    cp_commit();

    float d[2][8][4];
#pragma unroll
    for (int mt = 0; mt < 2; mt++)
#pragma unroll
        for (int nt = 0; nt < 8; nt++)
#pragma unroll
            for (int e = 0; e < 4; e++) d[mt][nt][e] = 0.f;

    for (int kt = 0; kt < 49; kt++) {
        if (kt < 48) {
            load_chunk((kt + 1) & 1, kz + (kt + 1) * 32);
            cp_commit();
            cp_wait1();
        } else {
            cp_wait0();
        }
        __syncthreads();

        const u32 abuf = sbase + (u32)(kt & 1) * 20480u;
        const u32 bbuf = sbase + 40960u + (u32)(kt & 1) * 20480u;

#pragma unroll
        for (int ks = 0; ks < 2; ks++) {
            u32 ah[2][4], al[2][4];
#pragma unroll
            for (int mt = 0; mt < 2; mt++) {
                u32 ar = abuf + ((u32)(wm * 32 + mt * 16) + arow16) * 80u
                       + (u32)ks * 32u + acb16;
                ldsm4(ah[mt][0], ah[mt][1], ah[mt][2], ah[mt][3], ar);
                ldsm4(al[mt][0], al[mt][1], al[mt][2], al[mt][3], ar + 10240u);
            }
            u32 bh[8][2], bl[8][2];
#pragma unroll
            for (int p = 0; p < 4; p++) {
                u32 ad = bbuf + ((u32)(wn * 64 + p * 16) + lrow) * 80u
                       + (u32)ks * 32u + lkb16;
                ldsm4(bh[2 * p][0], bh[2 * p][1], bh[2 * p + 1][0], bh[2 * p + 1][1], ad);
                ldsm4(bl[2 * p][0], bl[2 * p][1], bl[2 * p + 1][0], bl[2 * p + 1][1],
                      ad + 10240u);
            }
#pragma unroll
            for (int mt = 0; mt < 2; mt++)
#pragma unroll
                for (int nt = 0; nt < 8; nt++) mma16816(d[mt][nt], ah[mt], bh[nt]);
#pragma unroll
            for (int mt = 0; mt < 2; mt++)
#pragma unroll
                for (int nt = 0; nt < 8; nt++) mma16816(d[mt][nt], al[mt], bh[nt]);
#pragma unroll
            for (int mt = 0; mt < 2; mt++)
#pragma unroll
                for (int nt = 0; nt < 8; nt++) mma16816(d[mt][nt], ah[mt], bl[nt]);
        }
        __syncthreads();
    }

    float* outp = g_fc1p + (size_t)blockIdx.z * (2048 * 1024);
#pragma unroll
    for (int nt = 0; nt < 8; nt++) {
        int col = bn + wn * 64 + nt * 8 + (lane & 3) * 2;
#pragma unroll
        for (int mt = 0; mt < 2; mt++)
#pragma unroll
            for (int rp = 0; rp < 2; rp++) {
                int row = bm + wm * 32 + mt * 16 + (lane >> 2) + rp * 8;
                float2 o;
                o.x = d[mt][nt][2 * rp];
                o.y = d[mt][nt][2 * rp + 1];
                *reinterpret_cast<float2*>(&outp[(size_t)row * 1024 + col]) = o;
            }
    }
}

// ============================================================================
// fc2 fused, 2-warp k-split per row: a = relu(p0 + p1 + b1),
// out = a @ fc2_w^T + b2. Grid 512 CTAs x 8 warps = 2048 rows x 2 halves.
// ============================================================================
__global__ void __launch_bounds__(256) k_fc2(const float* __restrict__ w,
                                             const float* __restrict__ b1,
                                             const float* __restrict__ b2,
                                             float* __restrict__ out) {
    __shared__ float sb1[1024];
    __shared__ float sred[8][10];
    for (int i = threadIdx.x; i < 1024; i += 256) sb1[i] = b1[i];
    __syncthreads();

    int warp = threadIdx.x >> 5, lane = threadIdx.x & 31;
    int slot = blockIdx.x * 8 + warp;           // 4096 slots
    int row = slot >> 1, half = slot & 1;
    const float4* p0 = reinterpret_cast<const float4*>(g_fc1p + (size_t)row * 1024);
    const float4* p1 = reinterpret_cast<const float4*>(g_fc1p + 2048 * 1024 + (size_t)row * 1024);

    float acc[10];
#pragma unroll
    for (int n = 0; n < 10; n++) acc[n] = 0.f;

#pragma unroll
    for (int it = 0; it < 4; it++) {
        int k4 = half * 128 + it * 32 + lane;    // float4 index within row
        float4 a0 = p0[k4];
        float4 a1 = p1[k4];
        float4 bb = *reinterpret_cast<const float4*>(sb1 + k4 * 4);
        float4 av;
        av.x = fmaxf(a0.x + a1.x + bb.x, 0.f);
        av.y = fmaxf(a0.y + a1.y + bb.y, 0.f);
        av.z = fmaxf(a0.z + a1.z + bb.z, 0.f);
        av.w = fmaxf(a0.w + a1.w + bb.w, 0.f);
#pragma unroll
        for (int n = 0; n < 10; n++) {
            float4 wv = *reinterpret_cast<const float4*>(w + n * 1024 + k4 * 4);
            acc[n] += av.x * wv.x + av.y * wv.y + av.z * wv.z + av.w * wv.w;
        }
    }
#pragma unroll
    for (int n = 0; n < 10; n++)
#pragma unroll
        for (int off = 16; off > 0; off >>= 1)
            acc[n] += __shfl_xor_sync(0xffffffffu, acc[n], off);
    if (lane < 10) sred[warp][lane] = acc[lane];
    __syncthreads();
    if ((warp & 1) == 0 && lane < 10) {
        out[row * 10 + lane] = sred[warp][lane] + sred[warp + 1][lane] + b2[lane];
    }
}

// ============================================================================
extern "C" void kernel_launch(void* const* d_in, const int* in_sizes, int n_in,
                              void* d_out, int out_size) {
    const float* x       = (const float*)d_in[0];
    const float* conv1_w = (const float*)d_in[1];
    const float* trelu_t = (const float*)d_in[2];
    const float* conv2_w = (const float*)d_in[3];
    const float* conv2_b = (const float*)d_in[4];
    const float* fc1_w   = (const float*)d_in[5];
    const float* fc1_b   = (const float*)d_in[6];
    const float* fc2_w   = (const float*)d_in[7];
    const float* fc2_b   = (const float*)d_in[8];
    float* out = (float*)d_out;

    const int SMEM2 = 2 * 43008;
    const int SMEMF = 2 * 40960;
    cudaFuncSetAttribute(k_conv2, cudaFuncAttributeMaxDynamicSharedMemorySize, SMEM2);
    cudaFuncSetAttribute(k_fc1, cudaFuncAttributeMaxDynamicSharedMemorySize, SMEMF);

    k_conv1<<<2048 + 1024 + 138, 784>>>(x, conv1_w, trelu_t, conv2_w, fc1_w);
    k_conv2<<<1568, 256, SMEM2>>>(conv2_b);
    k_fc1<<<dim3(16, 8, 2), 256, SMEMF>>>(0);
    k_fc2<<<512, 256>>>(fc2_w, fc1_b, fc2_b, out);
}